// round 4
// baseline (speedup 1.0000x reference)
#include <cuda_runtime.h>
#include <cuda_bf16.h>
#include <stdint.h>

// Problem-size capacities (shapes fixed by the dataset)
#define MAXN 100000
#define MAXE 3200000
#define MAXT (MAXE + MAXN)   // edges + self loops
#define FDIM 128
#define SCAN_THREADS 1024

// ------------------- device scratch (no runtime allocation allowed) -------------------
__device__ __align__(16) float g_deg[MAXN];   // weighted degree (rsqrt fused into scatter)
__device__ int   g_count[MAXN];               // per-dest edge counts (incl self loop)
__device__ int   g_rowptr[MAXN + 1];          // CSR row pointers (by destination)
__device__ int   g_cursor[MAXN];              // scatter cursors
__device__ int   g_row[MAXE];                 // converted edge sources
__device__ int   g_col[MAXE];                 // converted edge destinations
__device__ __align__(16) int2 g_edge[MAXT];   // CSR slot: {src, __float_as_int(norm)}
__device__ __align__(16) float g_h1[(size_t)MAXN * FDIM];
__device__ __align__(16) float g_h2[(size_t)MAXN * FDIM];
__device__ __align__(16) float g_probe[(size_t)MAXN * FDIM];  // probe sink (never read)

// ------------------- init -------------------
__global__ void k_init(int N) {
    int i = blockIdx.x * blockDim.x + threadIdx.x;
    if (i < N) {
        g_count[i] = 1;       // self loop
        g_deg[i] = 1.0f;      // self loop weight
        g_cursor[i] = 0;
    }
}

// ------------------- decode indices (dtype robust) + degree/count atomics -------------------
__global__ void k_degcount(const void* __restrict__ ei_raw,
                           const float* __restrict__ ew, int E, int N) {
    const long long* p64 = (const long long*)ei_raw;
    __shared__ int is64;
    if (threadIdx.x == 0) {
        int ok = 1;
#pragma unroll
        for (int i = 0; i < 4; i++) {
            long long v = p64[i];
            if (v < 0 || v >= (long long)N) ok = 0;
        }
        is64 = ok;
    }
    __syncthreads();
    int e = blockIdx.x * blockDim.x + threadIdx.x;
    if (e >= E) return;
    int r, c;
    if (is64) {
        r = (int)p64[e];
        c = (int)p64[(size_t)E + e];
    } else {
        const int* p32 = (const int*)ei_raw;
        r = p32[e];
        c = p32[(size_t)E + e];
    }
    g_row[e] = r;
    g_col[e] = c;
    atomicAdd(&g_deg[c], ew[e]);
    atomicAdd(&g_count[c], 1);
}

// ------------------- single-block exclusive scan of g_count -> g_rowptr -------------------
__global__ void k_scan(int N, int total) {
    __shared__ int warpoff[32];
    __shared__ int s_running;
    int t = threadIdx.x;
    int wid = t >> 5, lid = t & 31;
    if (t == 0) s_running = 0;
    __syncthreads();
    int nchunk = (N + SCAN_THREADS - 1) / SCAN_THREADS;
    for (int ch = 0; ch < nchunk; ch++) {
        int i = ch * SCAN_THREADS + t;
        int v = (i < N) ? g_count[i] : 0;
        int s = v;
#pragma unroll
        for (int o = 1; o < 32; o <<= 1) {
            int u = __shfl_up_sync(0xFFFFFFFFu, s, o);
            if (lid >= o) s += u;
        }
        if (lid == 31) warpoff[wid] = s;
        __syncthreads();
        if (t < 32) {
            int w = warpoff[t];
            int sw = w;
#pragma unroll
            for (int o = 1; o < 32; o <<= 1) {
                int u = __shfl_up_sync(0xFFFFFFFFu, sw, o);
                if (t >= o) sw += u;
            }
            warpoff[t] = sw - w;
        }
        __syncthreads();
        int excl = (s - v) + warpoff[wid] + s_running;
        if (i < N) g_rowptr[i] = excl;
        __syncthreads();
        if (t == SCAN_THREADS - 1) s_running = excl + v;
        __syncthreads();
    }
    if (t == 0) g_rowptr[N] = total;
}

// ------------------- scatter edges + self-loops into CSR (norm fused) -------------------
__global__ void k_scatter(const float* __restrict__ ew, int E, int N) {
    int idx = blockIdx.x * blockDim.x + threadIdx.x;
    int total = E + N;
    if (idx >= total) return;
    int r, c;
    float w;
    if (idx < E) {
        r = g_row[idx];
        c = g_col[idx];
        w = ew[idx];
    } else {
        r = c = idx - E;
        w = 1.0f;
    }
    float nv = rsqrtf(g_deg[r]) * w * rsqrtf(g_deg[c]);
    int pos = g_rowptr[c] + atomicAdd(&g_cursor[c], 1);
    g_edge[pos] = make_int2(r, __float_as_int(nv));
}

// ------------------- dense GEMM: C[M,128] = A[M,128] @ W[128,128] -------------------
__global__ void k_gemm(const float* __restrict__ A, const float* __restrict__ W,
                       float* __restrict__ C, int M) {
    __shared__ float xs[64][33];
    __shared__ float ws[32][128];
    int tid = threadIdx.x;
    int tx = tid & 31;
    int ty = tid >> 5;
    int m0 = blockIdx.x * 64;

    float acc[8][4];
#pragma unroll
    for (int i = 0; i < 8; i++)
#pragma unroll
        for (int j = 0; j < 4; j++) acc[i][j] = 0.0f;

    for (int k0 = 0; k0 < 128; k0 += 32) {
#pragma unroll
        for (int i = 0; i < 2; i++) {
            int idx = tid + i * 256;
            int r = idx >> 3;
            int q = idx & 7;
            float4 v = make_float4(0.f, 0.f, 0.f, 0.f);
            int gm = m0 + r;
            if (gm < M)
                v = *(const float4*)(A + (size_t)gm * 128 + k0 + q * 4);
            xs[r][q * 4 + 0] = v.x;
            xs[r][q * 4 + 1] = v.y;
            xs[r][q * 4 + 2] = v.z;
            xs[r][q * 4 + 3] = v.w;
        }
#pragma unroll
        for (int i = 0; i < 4; i++) {
            int idx = tid + i * 256;
            int r = idx >> 5;
            int q = idx & 31;
            float4 v = *(const float4*)(W + (size_t)(k0 + r) * 128 + q * 4);
            *(float4*)&ws[r][q * 4] = v;
        }
        __syncthreads();
#pragma unroll
        for (int kk = 0; kk < 32; kk++) {
            float4 b = *(const float4*)&ws[kk][tx * 4];
#pragma unroll
            for (int i = 0; i < 8; i++) {
                float a = xs[ty * 8 + i][kk];
                acc[i][0] += a * b.x;
                acc[i][1] += a * b.y;
                acc[i][2] += a * b.z;
                acc[i][3] += a * b.w;
            }
        }
        __syncthreads();
    }
#pragma unroll
    for (int i = 0; i < 8; i++) {
        int gm = m0 + ty * 8 + i;
        if (gm < M) {
            float4 v = make_float4(acc[i][0], acc[i][1], acc[i][2], acc[i][3]);
            *(float4*)(C + (size_t)gm * 128 + tx * 4) = v;
        }
    }
}

// ------------------- SpMM: out[c,:] = sum val*h[src,:] + bias, optional relu ----------
__global__ void k_spmm(const float4* __restrict__ h,
                       const float* __restrict__ bias,
                       float* __restrict__ out, int N, int doRelu) {
    int warp = (blockIdx.x * blockDim.x + threadIdx.x) >> 5;
    int lane = threadIdx.x & 31;
    if (warp >= N) return;
    int beg = g_rowptr[warp];
    int end = g_rowptr[warp + 1];

    float4 acc = ((const float4*)bias)[lane];
    int e = beg;
    for (; e + 4 <= end; e += 4) {
        int2 p0 = g_edge[e + 0];
        int2 p1 = g_edge[e + 1];
        int2 p2 = g_edge[e + 2];
        int2 p3 = g_edge[e + 3];
        float4 h0 = h[(size_t)p0.x * 32 + lane];
        float4 h1 = h[(size_t)p1.x * 32 + lane];
        float4 h2 = h[(size_t)p2.x * 32 + lane];
        float4 h3 = h[(size_t)p3.x * 32 + lane];
        float v0 = __int_as_float(p0.y);
        float v1 = __int_as_float(p1.y);
        float v2 = __int_as_float(p2.y);
        float v3 = __int_as_float(p3.y);
        acc.x += v0 * h0.x; acc.y += v0 * h0.y; acc.z += v0 * h0.z; acc.w += v0 * h0.w;
        acc.x += v1 * h1.x; acc.y += v1 * h1.y; acc.z += v1 * h1.z; acc.w += v1 * h1.w;
        acc.x += v2 * h2.x; acc.y += v2 * h2.y; acc.z += v2 * h2.z; acc.w += v2 * h2.w;
        acc.x += v3 * h3.x; acc.y += v3 * h3.y; acc.z += v3 * h3.z; acc.w += v3 * h3.w;
    }
    for (; e < end; e++) {
        int2 p0 = g_edge[e];
        float4 h0 = h[(size_t)p0.x * 32 + lane];
        float v0 = __int_as_float(p0.y);
        acc.x += v0 * h0.x; acc.y += v0 * h0.y; acc.z += v0 * h0.z; acc.w += v0 * h0.w;
    }
    if (doRelu) {
        acc.x = fmaxf(acc.x, 0.f);
        acc.y = fmaxf(acc.y, 0.f);
        acc.z = fmaxf(acc.z, 0.f);
        acc.w = fmaxf(acc.w, 0.f);
    }
    *(float4*)(out + (size_t)warp * 128 + lane * 4) = acc;
}

// ------------------- launch -------------------
// PROBE ROUND: ncu captures launch #4 -> k_scatter profiled.
// +2 extra gemm runs, +6 extra spmm runs, all into g_probe (never read).
// dur ≈ base + 2*gemm + 6*spmm identifies the 17.3ms sink by magnitude:
//   ~20ms -> prep/overhead; ~36ms -> gemm; ~70ms -> spmm.
extern "C" void kernel_launch(void* const* d_in, const int* in_sizes, int n_in,
                              void* d_out, int out_size) {
    const float* x  = (const float*)d_in[0];
    const void*  ei = (const void*)d_in[1];
    const float* ew = (const float*)d_in[2];
    const float* W1 = (const float*)d_in[3];
    const float* b1 = (const float*)d_in[4];
    const float* W2 = (const float*)d_in[5];
    const float* b2 = (const float*)d_in[6];
    float* out = (float*)d_out;

    const int E = in_sizes[2];          // 3200000
    const int N = in_sizes[0] / FDIM;   // 100000
    const int T = E + N;

    int gemmGrid = (N + 63) / 64;
    int spmmGrid = (N * 32 + 255) / 256;

    k_init<<<(N + 255) / 256, 256>>>(N);                    // #1
    k_degcount<<<(E + 255) / 256, 256>>>(ei, ew, E, N);     // #2
    k_scan<<<1, SCAN_THREADS>>>(N, T);                      // #3
    k_scatter<<<(T + 255) / 256, 256>>>(ew, E, N);          // #4  <- ncu capture

    // --- layer 1 ---
    k_gemm<<<gemmGrid, 256>>>(x, W1, g_h1, N);              // #5
    k_gemm<<<gemmGrid, 256>>>(x, W1, g_probe, N);           // #6  gemm probe
    k_gemm<<<gemmGrid, 256>>>(x, W1, g_probe, N);           // #7  gemm probe
    k_spmm<<<spmmGrid, 256>>>((const float4*)g_h1, b1, g_h2, N, 1);     // #8
    k_spmm<<<spmmGrid, 256>>>((const float4*)g_h1, b1, g_probe, N, 1);  // #9  spmm probe
    k_spmm<<<spmmGrid, 256>>>((const float4*)g_h1, b1, g_probe, N, 1);  // #10 spmm probe
    k_spmm<<<spmmGrid, 256>>>((const float4*)g_h1, b1, g_probe, N, 1);  // #11 spmm probe

    // --- layer 2 ---
    k_gemm<<<gemmGrid, 256>>>(g_h2, W2, g_h1, N);           // #12
    k_spmm<<<spmmGrid, 256>>>((const float4*)g_h1, b2, out, N, 0);      // #13
    k_spmm<<<spmmGrid, 256>>>((const float4*)g_h1, b2, g_probe, N, 0);  // #14 spmm probe
    k_spmm<<<spmmGrid, 256>>>((const float4*)g_h1, b2, g_probe, N, 0);  // #15 spmm probe
    k_spmm<<<spmmGrid, 256>>>((const float4*)g_h1, b2, g_probe, N, 0);  // #16 spmm probe
}

// round 5
// speedup vs baseline: 3.4402x; 3.4402x over previous
#include <cuda_runtime.h>
#include <cuda_bf16.h>
#include <stdint.h>

#define MAXN 100000
#define MAXE 3200000
#define MAXT (MAXE + MAXN)
#define FDIM 128
#define SCAN_THREADS 1024

// ------------------- device scratch -------------------
__device__ __align__(16) float g_deg[MAXN];
__device__ int   g_count[MAXN];
__device__ int   g_rowptr[MAXN + 1];
__device__ int   g_cursor[MAXN];
__device__ int   g_row[MAXE];
__device__ int   g_col[MAXE];
__device__ __align__(16) int2 g_edge[MAXT];   // {src, __float_as_int(norm)}
__device__ __align__(16) float g_h1[(size_t)MAXN * FDIM];
__device__ __align__(16) float g_h2[(size_t)MAXN * FDIM];
__device__ __align__(16) float g_probe[(size_t)MAXN * FDIM];  // probe sink (never read)

// ------------------- init -------------------
__global__ void k_init(int N) {
    int i = blockIdx.x * blockDim.x + threadIdx.x;
    if (i < N) {
        g_count[i] = 1;
        g_deg[i] = 1.0f;
        g_cursor[i] = 0;
    }
}

// ------------------- decode indices (dtype robust) + degree/count atomics ----------
__global__ void k_degcount(const void* __restrict__ ei_raw,
                           const float* __restrict__ ew, int E, int N) {
    const long long* p64 = (const long long*)ei_raw;
    __shared__ int is64;
    if (threadIdx.x == 0) {
        int ok = 1;
#pragma unroll
        for (int i = 0; i < 4; i++) {
            long long v = p64[i];
            if (v < 0 || v >= (long long)N) ok = 0;
        }
        is64 = ok;
    }
    __syncthreads();
    int e = blockIdx.x * blockDim.x + threadIdx.x;
    if (e >= E) return;
    int r, c;
    if (is64) {
        r = (int)p64[e];
        c = (int)p64[(size_t)E + e];
    } else {
        const int* p32 = (const int*)ei_raw;
        r = p32[e];
        c = p32[(size_t)E + e];
    }
    g_row[e] = r;
    g_col[e] = c;
    atomicAdd(&g_deg[c], ew[e]);
    atomicAdd(&g_count[c], 1);
}

// ------------------- single-block exclusive scan -------------------
__global__ void k_scan(int N, int total) {
    __shared__ int warpoff[32];
    __shared__ int s_running;
    int t = threadIdx.x;
    int wid = t >> 5, lid = t & 31;
    if (t == 0) s_running = 0;
    __syncthreads();
    int nchunk = (N + SCAN_THREADS - 1) / SCAN_THREADS;
    for (int ch = 0; ch < nchunk; ch++) {
        int i = ch * SCAN_THREADS + t;
        int v = (i < N) ? g_count[i] : 0;
        int s = v;
#pragma unroll
        for (int o = 1; o < 32; o <<= 1) {
            int u = __shfl_up_sync(0xFFFFFFFFu, s, o);
            if (lid >= o) s += u;
        }
        if (lid == 31) warpoff[wid] = s;
        __syncthreads();
        if (t < 32) {
            int w = warpoff[t];
            int sw = w;
#pragma unroll
            for (int o = 1; o < 32; o <<= 1) {
                int u = __shfl_up_sync(0xFFFFFFFFu, sw, o);
                if (t >= o) sw += u;
            }
            warpoff[t] = sw - w;
        }
        __syncthreads();
        int excl = (s - v) + warpoff[wid] + s_running;
        if (i < N) g_rowptr[i] = excl;
        __syncthreads();
        if (t == SCAN_THREADS - 1) s_running = excl + v;
        __syncthreads();
    }
    if (t == 0) g_rowptr[N] = total;
}

// ------------------- scatter into CSR (norm fused) -------------------
__global__ void k_scatter(const float* __restrict__ ew, int E, int N) {
    int idx = blockIdx.x * blockDim.x + threadIdx.x;
    int total = E + N;
    if (idx >= total) return;
    int r, c;
    float w;
    if (idx < E) {
        r = g_row[idx];
        c = g_col[idx];
        w = ew[idx];
    } else {
        r = c = idx - E;
        w = 1.0f;
    }
    float nv = rsqrtf(g_deg[r]) * w * rsqrtf(g_deg[c]);
    int pos = g_rowptr[c] + atomicAdd(&g_cursor[c], 1);
    g_edge[pos] = make_int2(r, __float_as_int(nv));
}

// ------------------- dense GEMM: C[M,128] = A[M,128] @ W[128,128] -------------------
__global__ void k_gemm(const float* __restrict__ A, const float* __restrict__ W,
                       float* __restrict__ C, int M) {
    __shared__ float xs[64][33];
    __shared__ float ws[32][128];
    int tid = threadIdx.x;
    int tx = tid & 31;
    int ty = tid >> 5;
    int m0 = blockIdx.x * 64;

    float acc[8][4];
#pragma unroll
    for (int i = 0; i < 8; i++)
#pragma unroll
        for (int j = 0; j < 4; j++) acc[i][j] = 0.0f;

    for (int k0 = 0; k0 < 128; k0 += 32) {
#pragma unroll
        for (int i = 0; i < 2; i++) {
            int idx = tid + i * 256;
            int r = idx >> 3;
            int q = idx & 7;
            float4 v = make_float4(0.f, 0.f, 0.f, 0.f);
            int gm = m0 + r;
            if (gm < M)
                v = *(const float4*)(A + (size_t)gm * 128 + k0 + q * 4);
            xs[r][q * 4 + 0] = v.x;
            xs[r][q * 4 + 1] = v.y;
            xs[r][q * 4 + 2] = v.z;
            xs[r][q * 4 + 3] = v.w;
        }
#pragma unroll
        for (int i = 0; i < 4; i++) {
            int idx = tid + i * 256;
            int r = idx >> 5;
            int q = idx & 31;
            float4 v = *(const float4*)(W + (size_t)(k0 + r) * 128 + q * 4);
            *(float4*)&ws[r][q * 4] = v;
        }
        __syncthreads();
#pragma unroll
        for (int kk = 0; kk < 32; kk++) {
            float4 b = *(const float4*)&ws[kk][tx * 4];
#pragma unroll
            for (int i = 0; i < 8; i++) {
                float a = xs[ty * 8 + i][kk];
                acc[i][0] += a * b.x;
                acc[i][1] += a * b.y;
                acc[i][2] += a * b.z;
                acc[i][3] += a * b.w;
            }
        }
        __syncthreads();
    }
#pragma unroll
    for (int i = 0; i < 8; i++) {
        int gm = m0 + ty * 8 + i;
        if (gm < M) {
            float4 v = make_float4(acc[i][0], acc[i][1], acc[i][2], acc[i][3]);
            *(float4*)(C + (size_t)gm * 128 + tx * 4) = v;
        }
    }
}

// ------------------- SpMM: out[c,:] = sum val*h[src,:] + bias (+relu) ---------------
// Warp per node, lane owns float4. 8 independent gathers in flight; edges read 2/instr.
__global__ void __launch_bounds__(256) k_spmm(const float4* __restrict__ h,
                                              const float* __restrict__ bias,
                                              float* __restrict__ out, int N, int doRelu) {
    int warp = (blockIdx.x * blockDim.x + threadIdx.x) >> 5;
    int lane = threadIdx.x & 31;
    if (warp >= N) return;
    int beg = g_rowptr[warp];
    int end = g_rowptr[warp + 1];

    float4 acc = ((const float4*)bias)[lane];
    int e = beg;

    // align e to even for int4 (2-edge) loads
    if ((e & 1) && e < end) {
        int2 p = g_edge[e];
        float4 hv = h[(size_t)p.x * 32 + lane];
        float v = __int_as_float(p.y);
        acc.x += v * hv.x; acc.y += v * hv.y; acc.z += v * hv.z; acc.w += v * hv.w;
        e++;
    }

    // main loop: 8 edges per iteration, 8 gathers in flight
    for (; e + 8 <= end; e += 8) {
        int4 q0 = *(const int4*)&g_edge[e + 0];
        int4 q1 = *(const int4*)&g_edge[e + 2];
        int4 q2 = *(const int4*)&g_edge[e + 4];
        int4 q3 = *(const int4*)&g_edge[e + 6];
        float4 h0 = h[(size_t)q0.x * 32 + lane];
        float4 h1 = h[(size_t)q0.z * 32 + lane];
        float4 h2 = h[(size_t)q1.x * 32 + lane];
        float4 h3 = h[(size_t)q1.z * 32 + lane];
        float4 h4 = h[(size_t)q2.x * 32 + lane];
        float4 h5 = h[(size_t)q2.z * 32 + lane];
        float4 h6 = h[(size_t)q3.x * 32 + lane];
        float4 h7 = h[(size_t)q3.z * 32 + lane];
        float v0 = __int_as_float(q0.y), v1 = __int_as_float(q0.w);
        float v2 = __int_as_float(q1.y), v3 = __int_as_float(q1.w);
        float v4 = __int_as_float(q2.y), v5 = __int_as_float(q2.w);
        float v6 = __int_as_float(q3.y), v7 = __int_as_float(q3.w);
        acc.x += v0 * h0.x; acc.y += v0 * h0.y; acc.z += v0 * h0.z; acc.w += v0 * h0.w;
        acc.x += v1 * h1.x; acc.y += v1 * h1.y; acc.z += v1 * h1.z; acc.w += v1 * h1.w;
        acc.x += v2 * h2.x; acc.y += v2 * h2.y; acc.z += v2 * h2.z; acc.w += v2 * h2.w;
        acc.x += v3 * h3.x; acc.y += v3 * h3.y; acc.z += v3 * h3.z; acc.w += v3 * h3.w;
        acc.x += v4 * h4.x; acc.y += v4 * h4.y; acc.z += v4 * h4.z; acc.w += v4 * h4.w;
        acc.x += v5 * h5.x; acc.y += v5 * h5.y; acc.z += v5 * h5.z; acc.w += v5 * h5.w;
        acc.x += v6 * h6.x; acc.y += v6 * h6.y; acc.z += v6 * h6.z; acc.w += v6 * h6.w;
        acc.x += v7 * h7.x; acc.y += v7 * h7.y; acc.z += v7 * h7.z; acc.w += v7 * h7.w;
    }

    // 2-edge tail steps (e still even)
    for (; e + 2 <= end; e += 2) {
        int4 q0 = *(const int4*)&g_edge[e];
        float4 h0 = h[(size_t)q0.x * 32 + lane];
        float4 h1 = h[(size_t)q0.z * 32 + lane];
        float v0 = __int_as_float(q0.y), v1 = __int_as_float(q0.w);
        acc.x += v0 * h0.x; acc.y += v0 * h0.y; acc.z += v0 * h0.z; acc.w += v0 * h0.w;
        acc.x += v1 * h1.x; acc.y += v1 * h1.y; acc.z += v1 * h1.z; acc.w += v1 * h1.w;
    }
    if (e < end) {
        int2 p = g_edge[e];
        float4 hv = h[(size_t)p.x * 32 + lane];
        float v = __int_as_float(p.y);
        acc.x += v * hv.x; acc.y += v * hv.y; acc.z += v * hv.z; acc.w += v * hv.w;
    }

    if (doRelu) {
        acc.x = fmaxf(acc.x, 0.f);
        acc.y = fmaxf(acc.y, 0.f);
        acc.z = fmaxf(acc.z, 0.f);
        acc.w = fmaxf(acc.w, 0.f);
    }
    *(float4*)(out + (size_t)warp * 128 + lane * 4) = acc;
}

// ------------------- launch -------------------
// ncu captures launch #4 -> quarter-size k_spmm probe on stale-but-deterministic
// CSR data (identical every replay; zeros on the very first correctness call,
// output to g_probe which is never read).
extern "C" void kernel_launch(void* const* d_in, const int* in_sizes, int n_in,
                              void* d_out, int out_size) {
    const float* x  = (const float*)d_in[0];
    const void*  ei = (const void*)d_in[1];
    const float* ew = (const float*)d_in[2];
    const float* W1 = (const float*)d_in[3];
    const float* b1 = (const float*)d_in[4];
    const float* W2 = (const float*)d_in[5];
    const float* b2 = (const float*)d_in[6];
    float* out = (float*)d_out;

    const int E = in_sizes[2];          // 3200000
    const int N = in_sizes[0] / FDIM;   // 100000
    const int T = E + N;

    int gemmGrid = (N + 63) / 64;
    int spmmGrid = (N * 32 + 255) / 256;
    int probeN = N / 4;
    int probeGrid = (probeN * 32 + 255) / 256;

    k_init<<<(N + 255) / 256, 256>>>(N);                    // #1
    k_degcount<<<(E + 255) / 256, 256>>>(ei, ew, E, N);     // #2
    k_scan<<<1, SCAN_THREADS>>>(N, T);                      // #3
    k_spmm<<<probeGrid, 256>>>((const float4*)g_h1, b1, g_probe, probeN, 1);  // #4 <- ncu
    k_scatter<<<(T + 255) / 256, 256>>>(ew, E, N);          // #5

    k_gemm<<<gemmGrid, 256>>>(x, W1, g_h1, N);              // #6
    k_spmm<<<spmmGrid, 256>>>((const float4*)g_h1, b1, g_h2, N, 1);   // #7
    k_gemm<<<gemmGrid, 256>>>(g_h2, W2, g_h1, N);           // #8
    k_spmm<<<spmmGrid, 256>>>((const float4*)g_h1, b2, out, N, 0);    // #9
}

// round 6
// speedup vs baseline: 130.2157x; 37.8514x over previous
#include <cuda_runtime.h>
#include <cuda_bf16.h>
#include <stdint.h>

#define MAXN 100000
#define MAXE 3200000
#define MAXT (MAXE + MAXN)
#define FDIM 128
#define SCAN_THREADS 1024

// ------------------- device scratch -------------------
// NOTE: these symbols must ONLY be referenced from device code. Passing them
// as kernel args from host yields the host shadow symbol, which GB300's ATS
// happily serves from Grace DRAM at ~200 GB/s (the R2-R5 17.9ms bug).
__device__ __align__(16) float g_deg[MAXN];
__device__ int   g_count[MAXN];
__device__ int   g_rowptr[MAXN + 1];
__device__ int   g_cursor[MAXN];
__device__ int   g_row[MAXE];
__device__ int   g_col[MAXE];
__device__ __align__(16) int2 g_edge[MAXT];   // {src, __float_as_int(norm)}
__device__ __align__(16) float g_h1[(size_t)MAXN * FDIM];
__device__ __align__(16) float g_h2[(size_t)MAXN * FDIM];

// ------------------- init -------------------
__global__ void k_init(int N) {
    int i = blockIdx.x * blockDim.x + threadIdx.x;
    if (i < N) {
        g_count[i] = 1;
        g_deg[i] = 1.0f;
        g_cursor[i] = 0;
    }
}

// ------------------- decode indices (dtype robust) + degree/count atomics ----------
__global__ void k_degcount(const void* __restrict__ ei_raw,
                           const float* __restrict__ ew, int E, int N) {
    const long long* p64 = (const long long*)ei_raw;
    __shared__ int is64;
    if (threadIdx.x == 0) {
        int ok = 1;
#pragma unroll
        for (int i = 0; i < 4; i++) {
            long long v = p64[i];
            if (v < 0 || v >= (long long)N) ok = 0;
        }
        is64 = ok;
    }
    __syncthreads();
    int e = blockIdx.x * blockDim.x + threadIdx.x;
    if (e >= E) return;
    int r, c;
    if (is64) {
        r = (int)p64[e];
        c = (int)p64[(size_t)E + e];
    } else {
        const int* p32 = (const int*)ei_raw;
        r = p32[e];
        c = p32[(size_t)E + e];
    }
    g_row[e] = r;
    g_col[e] = c;
    atomicAdd(&g_deg[c], ew[e]);
    atomicAdd(&g_count[c], 1);
}

// ------------------- single-block exclusive scan -------------------
__global__ void k_scan(int N, int total) {
    __shared__ int warpoff[32];
    __shared__ int s_running;
    int t = threadIdx.x;
    int wid = t >> 5, lid = t & 31;
    if (t == 0) s_running = 0;
    __syncthreads();
    int nchunk = (N + SCAN_THREADS - 1) / SCAN_THREADS;
    for (int ch = 0; ch < nchunk; ch++) {
        int i = ch * SCAN_THREADS + t;
        int v = (i < N) ? g_count[i] : 0;
        int s = v;
#pragma unroll
        for (int o = 1; o < 32; o <<= 1) {
            int u = __shfl_up_sync(0xFFFFFFFFu, s, o);
            if (lid >= o) s += u;
        }
        if (lid == 31) warpoff[wid] = s;
        __syncthreads();
        if (t < 32) {
            int w = warpoff[t];
            int sw = w;
#pragma unroll
            for (int o = 1; o < 32; o <<= 1) {
                int u = __shfl_up_sync(0xFFFFFFFFu, sw, o);
                if (t >= o) sw += u;
            }
            warpoff[t] = sw - w;
        }
        __syncthreads();
        int excl = (s - v) + warpoff[wid] + s_running;
        if (i < N) g_rowptr[i] = excl;
        __syncthreads();
        if (t == SCAN_THREADS - 1) s_running = excl + v;
        __syncthreads();
    }
    if (t == 0) g_rowptr[N] = total;
}

// ------------------- scatter into CSR (norm fused) -------------------
__global__ void k_scatter(const float* __restrict__ ew, int E, int N) {
    int idx = blockIdx.x * blockDim.x + threadIdx.x;
    int total = E + N;
    if (idx >= total) return;
    int r, c;
    float w;
    if (idx < E) {
        r = g_row[idx];
        c = g_col[idx];
        w = ew[idx];
    } else {
        r = c = idx - E;
        w = 1.0f;
    }
    float nv = rsqrtf(g_deg[r]) * w * rsqrtf(g_deg[c]);
    int pos = g_rowptr[c] + atomicAdd(&g_cursor[c], 1);
    g_edge[pos] = make_int2(r, __float_as_int(nv));
}

// ------------------- dense GEMM: g_h1[M,128] = A[M,128] @ W[128,128] ----------------
// A = Aopt (harness input) or g_h2 (device symbol) when Aopt == nullptr.
__global__ void k_gemm(const float* __restrict__ Aopt, const float* __restrict__ W,
                       int M) {
    const float* A = Aopt ? Aopt : g_h2;
    float* C = g_h1;                       // device symbol, bound in device code
    __shared__ float xs[64][33];
    __shared__ float ws[32][128];
    int tid = threadIdx.x;
    int tx = tid & 31;
    int ty = tid >> 5;
    int m0 = blockIdx.x * 64;

    float acc[8][4];
#pragma unroll
    for (int i = 0; i < 8; i++)
#pragma unroll
        for (int j = 0; j < 4; j++) acc[i][j] = 0.0f;

    for (int k0 = 0; k0 < 128; k0 += 32) {
#pragma unroll
        for (int i = 0; i < 2; i++) {
            int idx = tid + i * 256;
            int r = idx >> 3;
            int q = idx & 7;
            float4 v = make_float4(0.f, 0.f, 0.f, 0.f);
            int gm = m0 + r;
            if (gm < M)
                v = *(const float4*)(A + (size_t)gm * 128 + k0 + q * 4);
            xs[r][q * 4 + 0] = v.x;
            xs[r][q * 4 + 1] = v.y;
            xs[r][q * 4 + 2] = v.z;
            xs[r][q * 4 + 3] = v.w;
        }
#pragma unroll
        for (int i = 0; i < 4; i++) {
            int idx = tid + i * 256;
            int r = idx >> 5;
            int q = idx & 31;
            float4 v = *(const float4*)(W + (size_t)(k0 + r) * 128 + q * 4);
            *(float4*)&ws[r][q * 4] = v;
        }
        __syncthreads();
#pragma unroll
        for (int kk = 0; kk < 32; kk++) {
            float4 b = *(const float4*)&ws[kk][tx * 4];
#pragma unroll
            for (int i = 0; i < 8; i++) {
                float a = xs[ty * 8 + i][kk];
                acc[i][0] += a * b.x;
                acc[i][1] += a * b.y;
                acc[i][2] += a * b.z;
                acc[i][3] += a * b.w;
            }
        }
        __syncthreads();
    }
#pragma unroll
    for (int i = 0; i < 8; i++) {
        int gm = m0 + ty * 8 + i;
        if (gm < M) {
            float4 v = make_float4(acc[i][0], acc[i][1], acc[i][2], acc[i][3]);
            *(float4*)(C + (size_t)gm * 128 + tx * 4) = v;
        }
    }
}

// ------------------- SpMM: out[c,:] = sum val*g_h1[src,:] + bias (+relu) ------------
// h = g_h1 (device symbol). out = outOpt (harness d_out) or g_h2 when nullptr.
__global__ void __launch_bounds__(256) k_spmm(const float* __restrict__ bias,
                                              float* outOpt, int N, int doRelu) {
    const float4* h = (const float4*)g_h1;
    float* out = outOpt ? outOpt : g_h2;
    int warp = (blockIdx.x * blockDim.x + threadIdx.x) >> 5;
    int lane = threadIdx.x & 31;
    if (warp >= N) return;
    int beg = g_rowptr[warp];
    int end = g_rowptr[warp + 1];

    float4 acc = ((const float4*)bias)[lane];
    int e = beg;

    // align e to even for int4 (2-edge) loads
    if ((e & 1) && e < end) {
        int2 p = g_edge[e];
        float4 hv = h[(size_t)p.x * 32 + lane];
        float v = __int_as_float(p.y);
        acc.x += v * hv.x; acc.y += v * hv.y; acc.z += v * hv.z; acc.w += v * hv.w;
        e++;
    }

    for (; e + 8 <= end; e += 8) {
        int4 q0 = *(const int4*)&g_edge[e + 0];
        int4 q1 = *(const int4*)&g_edge[e + 2];
        int4 q2 = *(const int4*)&g_edge[e + 4];
        int4 q3 = *(const int4*)&g_edge[e + 6];
        float4 h0 = h[(size_t)q0.x * 32 + lane];
        float4 h1 = h[(size_t)q0.z * 32 + lane];
        float4 h2 = h[(size_t)q1.x * 32 + lane];
        float4 h3 = h[(size_t)q1.z * 32 + lane];
        float4 h4 = h[(size_t)q2.x * 32 + lane];
        float4 h5 = h[(size_t)q2.z * 32 + lane];
        float4 h6 = h[(size_t)q3.x * 32 + lane];
        float4 h7 = h[(size_t)q3.z * 32 + lane];
        float v0 = __int_as_float(q0.y), v1 = __int_as_float(q0.w);
        float v2 = __int_as_float(q1.y), v3 = __int_as_float(q1.w);
        float v4 = __int_as_float(q2.y), v5 = __int_as_float(q2.w);
        float v6 = __int_as_float(q3.y), v7 = __int_as_float(q3.w);
        acc.x += v0 * h0.x; acc.y += v0 * h0.y; acc.z += v0 * h0.z; acc.w += v0 * h0.w;
        acc.x += v1 * h1.x; acc.y += v1 * h1.y; acc.z += v1 * h1.z; acc.w += v1 * h1.w;
        acc.x += v2 * h2.x; acc.y += v2 * h2.y; acc.z += v2 * h2.z; acc.w += v2 * h2.w;
        acc.x += v3 * h3.x; acc.y += v3 * h3.y; acc.z += v3 * h3.z; acc.w += v3 * h3.w;
        acc.x += v4 * h4.x; acc.y += v4 * h4.y; acc.z += v4 * h4.z; acc.w += v4 * h4.w;
        acc.x += v5 * h5.x; acc.y += v5 * h5.y; acc.z += v5 * h5.z; acc.w += v5 * h5.w;
        acc.x += v6 * h6.x; acc.y += v6 * h6.y; acc.z += v6 * h6.z; acc.w += v6 * h6.w;
        acc.x += v7 * h7.x; acc.y += v7 * h7.y; acc.z += v7 * h7.z; acc.w += v7 * h7.w;
    }

    for (; e + 2 <= end; e += 2) {
        int4 q0 = *(const int4*)&g_edge[e];
        float4 h0 = h[(size_t)q0.x * 32 + lane];
        float4 h1 = h[(size_t)q0.z * 32 + lane];
        float v0 = __int_as_float(q0.y), v1 = __int_as_float(q0.w);
        acc.x += v0 * h0.x; acc.y += v0 * h0.y; acc.z += v0 * h0.z; acc.w += v0 * h0.w;
        acc.x += v1 * h1.x; acc.y += v1 * h1.y; acc.z += v1 * h1.z; acc.w += v1 * h1.w;
    }
    if (e < end) {
        int2 p = g_edge[e];
        float4 hv = h[(size_t)p.x * 32 + lane];
        float v = __int_as_float(p.y);
        acc.x += v * hv.x; acc.y += v * hv.y; acc.z += v * hv.z; acc.w += v * hv.w;
    }

    if (doRelu) {
        acc.x = fmaxf(acc.x, 0.f);
        acc.y = fmaxf(acc.y, 0.f);
        acc.z = fmaxf(acc.z, 0.f);
        acc.w = fmaxf(acc.w, 0.f);
    }
    *(float4*)(out + (size_t)warp * 128 + lane * 4) = acc;
}

// ------------------- launch -------------------
// Launch #4 = gemm1: ncu captures a real heavy kernel this time.
extern "C" void kernel_launch(void* const* d_in, const int* in_sizes, int n_in,
                              void* d_out, int out_size) {
    const float* x  = (const float*)d_in[0];
    const void*  ei = (const void*)d_in[1];
    const float* ew = (const float*)d_in[2];
    const float* W1 = (const float*)d_in[3];
    const float* b1 = (const float*)d_in[4];
    const float* W2 = (const float*)d_in[5];
    const float* b2 = (const float*)d_in[6];
    float* out = (float*)d_out;

    const int E = in_sizes[2];          // 3200000
    const int N = in_sizes[0] / FDIM;   // 100000
    const int T = E + N;

    int gemmGrid = (N + 63) / 64;
    int spmmGrid = (N * 32 + 255) / 256;

    k_init<<<(N + 255) / 256, 256>>>(N);                    // #1
    k_degcount<<<(E + 255) / 256, 256>>>(ei, ew, E, N);     // #2
    k_scan<<<1, SCAN_THREADS>>>(N, T);                      // #3
    k_gemm<<<gemmGrid, 256>>>(x, W1, N);                    // #4  <- ncu capture
    k_scatter<<<(T + 255) / 256, 256>>>(ew, E, N);          // #5

    k_spmm<<<spmmGrid, 256>>>(b1, nullptr, N, 1);           // #6  g_h1 -> g_h2
    k_gemm<<<gemmGrid, 256>>>(nullptr, W2, N);              // #7  g_h2 -> g_h1
    k_spmm<<<spmmGrid, 256>>>(b2, out, N, 0);               // #8  g_h1 -> out
}

// round 7
// speedup vs baseline: 131.7543x; 1.0118x over previous
#include <cuda_runtime.h>
#include <cuda_bf16.h>
#include <stdint.h>

#define MAXN 100000
#define MAXE 3200000
#define MAXT (MAXE + MAXN)
#define FDIM 128
#define SCAN_THREADS 1024

// ------------------- device scratch -------------------
// NOTE: these symbols must ONLY be referenced from device code. Passing them
// as kernel args from host yields the host shadow symbol, which GB300's ATS
// serves from Grace DRAM at ~200 GB/s (the R2-R5 17.9ms bug).
__device__ __align__(16) float g_deg[MAXN];
__device__ int   g_count[MAXN];
__device__ int   g_rowptr[MAXN + 1];
__device__ int   g_cursor[MAXN];
__device__ __align__(16) int2 g_edge[MAXT];   // {src, __float_as_int(norm)}
__device__ __align__(16) float g_h1[(size_t)MAXN * FDIM];
__device__ __align__(16) float g_h2[(size_t)MAXN * FDIM];

// ------------------- dtype sniff helper (int64 vs int32 edge_index) -------------------
__device__ __forceinline__ int sniff_is64(const void* ei_raw, int N) {
    const long long* p64 = (const long long*)ei_raw;
    int ok = 1;
#pragma unroll
    for (int i = 0; i < 4; i++) {
        long long v = p64[i];
        if (v < 0 || v >= (long long)N) ok = 0;
    }
    return ok;
}

// ------------------- init -------------------
__global__ void k_init(int N) {
    int i = blockIdx.x * blockDim.x + threadIdx.x;
    if (i < N) {
        g_count[i] = 1;      // self loop
        g_deg[i] = 1.0f;     // self loop weight
        g_cursor[i] = 0;
    }
}

// ------------------- degree/count atomics over col -------------------
__global__ void k_degcount(const void* __restrict__ ei_raw,
                           const float* __restrict__ ew, int E, int N) {
    __shared__ int is64;
    if (threadIdx.x == 0) is64 = sniff_is64(ei_raw, N);
    __syncthreads();
    int e = blockIdx.x * blockDim.x + threadIdx.x;
    if (e >= E) return;
    int c;
    if (is64) c = (int)((const long long*)ei_raw)[(size_t)E + e];
    else      c = ((const int*)ei_raw)[(size_t)E + e];
    atomicAdd(&g_deg[c], ew[e]);
    atomicAdd(&g_count[c], 1);
}

// ------------------- single-block exclusive scan of g_count -> g_rowptr -------------------
__global__ void k_scan(int N, int total) {
    __shared__ int warpoff[32];
    __shared__ int s_running;
    int t = threadIdx.x;
    int wid = t >> 5, lid = t & 31;
    if (t == 0) s_running = 0;
    __syncthreads();
    int nchunk = (N + SCAN_THREADS - 1) / SCAN_THREADS;
    for (int ch = 0; ch < nchunk; ch++) {
        int i = ch * SCAN_THREADS + t;
        int v = (i < N) ? g_count[i] : 0;
        int s = v;
#pragma unroll
        for (int o = 1; o < 32; o <<= 1) {
            int u = __shfl_up_sync(0xFFFFFFFFu, s, o);
            if (lid >= o) s += u;
        }
        if (lid == 31) warpoff[wid] = s;
        __syncthreads();
        if (t < 32) {
            int w = warpoff[t];
            int sw = w;
#pragma unroll
            for (int o = 1; o < 32; o <<= 1) {
                int u = __shfl_up_sync(0xFFFFFFFFu, sw, o);
                if (t >= o) sw += u;
            }
            warpoff[t] = sw - w;
        }
        __syncthreads();
        int excl = (s - v) + warpoff[wid] + s_running;
        if (i < N) g_rowptr[i] = excl;
        __syncthreads();
        if (t == SCAN_THREADS - 1) s_running = excl + v;
        __syncthreads();
    }
    if (t == 0) g_rowptr[N] = total;
}

// ------------------- scatter into CSR (decode + norm fused) -------------------
__global__ void k_scatter(const void* __restrict__ ei_raw,
                          const float* __restrict__ ew, int E, int N) {
    __shared__ int is64;
    if (threadIdx.x == 0) is64 = sniff_is64(ei_raw, N);
    __syncthreads();
    int idx = blockIdx.x * blockDim.x + threadIdx.x;
    int total = E + N;
    if (idx >= total) return;
    int r, c;
    float w;
    if (idx < E) {
        if (is64) {
            const long long* p64 = (const long long*)ei_raw;
            r = (int)p64[idx];
            c = (int)p64[(size_t)E + idx];
        } else {
            const int* p32 = (const int*)ei_raw;
            r = p32[idx];
            c = p32[(size_t)E + idx];
        }
        w = ew[idx];
    } else {
        r = c = idx - E;
        w = 1.0f;
    }
    float nv = rsqrtf(g_deg[r]) * w * rsqrtf(g_deg[c]);
    int pos = g_rowptr[c] + atomicAdd(&g_cursor[c], 1);
    g_edge[pos] = make_int2(r, __float_as_int(nv));
}

// ------------------- dense GEMM: g_h1[M,128] = A[M,128] @ W[128,128] ----------------
// 128x128 block tile, 256 threads (16x16), 8x8 per-thread tile in 4+4 split
// (rows {ty*4, 64+ty*4}, cols {tx*4, 64+tx*4}) for conflict-free LDS.128.
__global__ void __launch_bounds__(256) k_gemm(const float* __restrict__ Aopt,
                                              const float* __restrict__ W, int M) {
    const float* A = Aopt ? Aopt : g_h2;
    float* C = g_h1;
    __shared__ float xs[16][132];   // [k][m] transposed A tile (132: 2-way STS, aligned LDS.128)
    __shared__ float ws[16][128];   // [k][n]
    int tid = threadIdx.x;
    int tx = tid & 15;              // col group
    int ty = tid >> 4;              // row group
    int m0 = blockIdx.x * 128;

    float acc[8][8];
#pragma unroll
    for (int i = 0; i < 8; i++)
#pragma unroll
        for (int j = 0; j < 8; j++) acc[i][j] = 0.0f;

    for (int k0 = 0; k0 < 128; k0 += 16) {
        // A tile: 128 rows x 16 k = 512 float4 (2/thread), store k-transposed
#pragma unroll
        for (int i = 0; i < 2; i++) {
            int idx = tid + i * 256;   // 0..511
            int r = idx >> 2;          // row 0..127
            int q = idx & 3;           // k-quad 0..3
            float4 v = make_float4(0.f, 0.f, 0.f, 0.f);
            if (m0 + r < M)
                v = *(const float4*)(A + (size_t)(m0 + r) * 128 + k0 + q * 4);
            xs[q * 4 + 0][r] = v.x;
            xs[q * 4 + 1][r] = v.y;
            xs[q * 4 + 2][r] = v.z;
            xs[q * 4 + 3][r] = v.w;
        }
        // B tile: 16 rows x 128 = 512 float4 (2/thread)
#pragma unroll
        for (int i = 0; i < 2; i++) {
            int idx = tid + i * 256;
            int r = idx >> 5;          // 0..15
            int q = idx & 31;
            *(float4*)&ws[r][q * 4] = *(const float4*)(W + (size_t)(k0 + r) * 128 + q * 4);
        }
        __syncthreads();
#pragma unroll
        for (int kk = 0; kk < 16; kk++) {
            float a[8], b[8];
            *(float4*)&a[0] = *(const float4*)&xs[kk][ty * 4];
            *(float4*)&a[4] = *(const float4*)&xs[kk][64 + ty * 4];
            *(float4*)&b[0] = *(const float4*)&ws[kk][tx * 4];
            *(float4*)&b[4] = *(const float4*)&ws[kk][64 + tx * 4];
#pragma unroll
            for (int i = 0; i < 8; i++)
#pragma unroll
                for (int j = 0; j < 8; j++)
                    acc[i][j] += a[i] * b[j];
        }
        __syncthreads();
    }
    // epilogue: rows m0 + {ty*4+i, 64+ty*4+i}, cols {tx*4, 64+tx*4}
#pragma unroll
    for (int hi = 0; hi < 2; hi++) {
#pragma unroll
        for (int i = 0; i < 4; i++) {
            int gm = m0 + hi * 64 + ty * 4 + i;
            if (gm < M) {
                int ai = hi * 4 + i;
                *(float4*)(C + (size_t)gm * 128 + tx * 4) =
                    make_float4(acc[ai][0], acc[ai][1], acc[ai][2], acc[ai][3]);
                *(float4*)(C + (size_t)gm * 128 + 64 + tx * 4) =
                    make_float4(acc[ai][4], acc[ai][5], acc[ai][6], acc[ai][7]);
            }
        }
    }
}

// ------------------- SpMM: out[c,:] = sum val*g_h1[src,:] + bias (+relu) ------------
__global__ void __launch_bounds__(256) k_spmm(const float* __restrict__ bias,
                                              float* outOpt, int N, int doRelu) {
    const float4* h = (const float4*)g_h1;
    float* out = outOpt ? outOpt : g_h2;
    int warp = (blockIdx.x * blockDim.x + threadIdx.x) >> 5;
    int lane = threadIdx.x & 31;
    if (warp >= N) return;
    int beg = g_rowptr[warp];
    int end = g_rowptr[warp + 1];

    float4 acc = ((const float4*)bias)[lane];
    int e = beg;

    if ((e & 1) && e < end) {
        int2 p = g_edge[e];
        float4 hv = h[(size_t)p.x * 32 + lane];
        float v = __int_as_float(p.y);
        acc.x += v * hv.x; acc.y += v * hv.y; acc.z += v * hv.z; acc.w += v * hv.w;
        e++;
    }

    for (; e + 8 <= end; e += 8) {
        int4 q0 = *(const int4*)&g_edge[e + 0];
        int4 q1 = *(const int4*)&g_edge[e + 2];
        int4 q2 = *(const int4*)&g_edge[e + 4];
        int4 q3 = *(const int4*)&g_edge[e + 6];
        float4 h0 = h[(size_t)q0.x * 32 + lane];
        float4 h1 = h[(size_t)q0.z * 32 + lane];
        float4 h2 = h[(size_t)q1.x * 32 + lane];
        float4 h3 = h[(size_t)q1.z * 32 + lane];
        float4 h4 = h[(size_t)q2.x * 32 + lane];
        float4 h5 = h[(size_t)q2.z * 32 + lane];
        float4 h6 = h[(size_t)q3.x * 32 + lane];
        float4 h7 = h[(size_t)q3.z * 32 + lane];
        float v0 = __int_as_float(q0.y), v1 = __int_as_float(q0.w);
        float v2 = __int_as_float(q1.y), v3 = __int_as_float(q1.w);
        float v4 = __int_as_float(q2.y), v5 = __int_as_float(q2.w);
        float v6 = __int_as_float(q3.y), v7 = __int_as_float(q3.w);
        acc.x += v0 * h0.x; acc.y += v0 * h0.y; acc.z += v0 * h0.z; acc.w += v0 * h0.w;
        acc.x += v1 * h1.x; acc.y += v1 * h1.y; acc.z += v1 * h1.z; acc.w += v1 * h1.w;
        acc.x += v2 * h2.x; acc.y += v2 * h2.y; acc.z += v2 * h2.z; acc.w += v2 * h2.w;
        acc.x += v3 * h3.x; acc.y += v3 * h3.y; acc.z += v3 * h3.z; acc.w += v3 * h3.w;
        acc.x += v4 * h4.x; acc.y += v4 * h4.y; acc.z += v4 * h4.z; acc.w += v4 * h4.w;
        acc.x += v5 * h5.x; acc.y += v5 * h5.y; acc.z += v5 * h5.z; acc.w += v5 * h5.w;
        acc.x += v6 * h6.x; acc.y += v6 * h6.y; acc.z += v6 * h6.z; acc.w += v6 * h6.w;
        acc.x += v7 * h7.x; acc.y += v7 * h7.y; acc.z += v7 * h7.z; acc.w += v7 * h7.w;
    }

    for (; e + 2 <= end; e += 2) {
        int4 q0 = *(const int4*)&g_edge[e];
        float4 h0 = h[(size_t)q0.x * 32 + lane];
        float4 h1 = h[(size_t)q0.z * 32 + lane];
        float v0 = __int_as_float(q0.y), v1 = __int_as_float(q0.w);
        acc.x += v0 * h0.x; acc.y += v0 * h0.y; acc.z += v0 * h0.z; acc.w += v0 * h0.w;
        acc.x += v1 * h1.x; acc.y += v1 * h1.y; acc.z += v1 * h1.z; acc.w += v1 * h1.w;
    }
    if (e < end) {
        int2 p = g_edge[e];
        float4 hv = h[(size_t)p.x * 32 + lane];
        float v = __int_as_float(p.y);
        acc.x += v * hv.x; acc.y += v * hv.y; acc.z += v * hv.z; acc.w += v * hv.w;
    }

    if (doRelu) {
        acc.x = fmaxf(acc.x, 0.f);
        acc.y = fmaxf(acc.y, 0.f);
        acc.z = fmaxf(acc.z, 0.f);
        acc.w = fmaxf(acc.w, 0.f);
    }
    *(float4*)(out + (size_t)warp * 128 + lane * 4) = acc;
}

// ------------------- launch -------------------
// Launch #4 = NEW gemm: ncu verifies the fma%/dur prediction.
extern "C" void kernel_launch(void* const* d_in, const int* in_sizes, int n_in,
                              void* d_out, int out_size) {
    const float* x  = (const float*)d_in[0];
    const void*  ei = (const void*)d_in[1];
    const float* ew = (const float*)d_in[2];
    const float* W1 = (const float*)d_in[3];
    const float* b1 = (const float*)d_in[4];
    const float* W2 = (const float*)d_in[5];
    const float* b2 = (const float*)d_in[6];
    float* out = (float*)d_out;

    const int E = in_sizes[2];          // 3200000
    const int N = in_sizes[0] / FDIM;   // 100000
    const int T = E + N;

    int gemmGrid = (N + 127) / 128;
    int spmmGrid = (N * 32 + 255) / 256;

    k_init<<<(N + 255) / 256, 256>>>(N);                    // #1
    k_degcount<<<(E + 255) / 256, 256>>>(ei, ew, E, N);     // #2
    k_scan<<<1, SCAN_THREADS>>>(N, T);                      // #3
    k_gemm<<<gemmGrid, 256>>>(x, W1, N);                    // #4  <- ncu capture
    k_scatter<<<(T + 255) / 256, 256>>>(ei, ew, E, N);      // #5

    k_spmm<<<spmmGrid, 256>>>(b1, nullptr, N, 1);           // #6  g_h1 -> g_h2
    k_gemm<<<gemmGrid, 256>>>(nullptr, W2, N);              // #7  g_h2 -> g_h1
    k_spmm<<<spmmGrid, 256>>>(b2, out, N, 0);               // #8  g_h1 -> out
}

// round 8
// speedup vs baseline: 146.5233x; 1.1121x over previous
#include <cuda_runtime.h>
#include <cuda_bf16.h>
#include <stdint.h>

#define MAXN 100000
#define MAXE 3200000
#define MAXT (MAXE + MAXN)
#define FDIM 128
#define SCAN_THREADS 1024

// ------------------- device scratch -------------------
// NOTE: these symbols must ONLY be referenced from device code. Passing them
// as kernel args from host yields the host shadow symbol, which GB300's ATS
// serves from Grace DRAM at ~200 GB/s (the R2-R5 17.9ms bug).
__device__ __align__(16) float g_deg[MAXN];
__device__ int   g_count[MAXN];
__device__ int   g_rowptr[MAXN + 1];
__device__ int   g_cursor[MAXN];
__device__ __align__(16) int2 g_edge[MAXT];   // {src, __float_as_int(norm)}
__device__ __align__(16) float g_h1[(size_t)MAXN * FDIM];
__device__ __align__(16) float g_h2[(size_t)MAXN * FDIM];

// ------------------- dtype sniff helper (int64 vs int32 edge_index) -------------------
__device__ __forceinline__ int sniff_is64(const void* ei_raw, int N) {
    const long long* p64 = (const long long*)ei_raw;
    int ok = 1;
#pragma unroll
    for (int i = 0; i < 4; i++) {
        long long v = p64[i];
        if (v < 0 || v >= (long long)N) ok = 0;
    }
    return ok;
}

// ------------------- init -------------------
__global__ void k_init(int N) {
    int i = blockIdx.x * blockDim.x + threadIdx.x;
    if (i < N) {
        g_count[i] = 1;      // self loop
        g_deg[i] = 1.0f;     // self loop weight
        g_cursor[i] = 0;
    }
}

// ------------------- degree/count atomics over col -------------------
__global__ void k_degcount(const void* __restrict__ ei_raw,
                           const float* __restrict__ ew, int E, int N) {
    __shared__ int is64;
    if (threadIdx.x == 0) is64 = sniff_is64(ei_raw, N);
    __syncthreads();
    int e = blockIdx.x * blockDim.x + threadIdx.x;
    if (e >= E) return;
    int c;
    if (is64) c = (int)((const long long*)ei_raw)[(size_t)E + e];
    else      c = ((const int*)ei_raw)[(size_t)E + e];
    atomicAdd(&g_deg[c], ew[e]);
    atomicAdd(&g_count[c], 1);
}

// ------------------- single-block exclusive scan of g_count -> g_rowptr -------------------
__global__ void k_scan(int N, int total) {
    __shared__ int warpoff[32];
    __shared__ int s_running;
    int t = threadIdx.x;
    int wid = t >> 5, lid = t & 31;
    if (t == 0) s_running = 0;
    __syncthreads();
    int nchunk = (N + SCAN_THREADS - 1) / SCAN_THREADS;
    for (int ch = 0; ch < nchunk; ch++) {
        int i = ch * SCAN_THREADS + t;
        int v = (i < N) ? g_count[i] : 0;
        int s = v;
#pragma unroll
        for (int o = 1; o < 32; o <<= 1) {
            int u = __shfl_up_sync(0xFFFFFFFFu, s, o);
            if (lid >= o) s += u;
        }
        if (lid == 31) warpoff[wid] = s;
        __syncthreads();
        if (t < 32) {
            int w = warpoff[t];
            int sw = w;
#pragma unroll
            for (int o = 1; o < 32; o <<= 1) {
                int u = __shfl_up_sync(0xFFFFFFFFu, sw, o);
                if (t >= o) sw += u;
            }
            warpoff[t] = sw - w;
        }
        __syncthreads();
        int excl = (s - v) + warpoff[wid] + s_running;
        if (i < N) g_rowptr[i] = excl;
        __syncthreads();
        if (t == SCAN_THREADS - 1) s_running = excl + v;
        __syncthreads();
    }
    if (t == 0) g_rowptr[N] = total;
}

// ------------------- scatter into CSR (decode + norm fused) -------------------
__global__ void k_scatter(const void* __restrict__ ei_raw,
                          const float* __restrict__ ew, int E, int N) {
    __shared__ int is64;
    if (threadIdx.x == 0) is64 = sniff_is64(ei_raw, N);
    __syncthreads();
    int idx = blockIdx.x * blockDim.x + threadIdx.x;
    int total = E + N;
    if (idx >= total) return;
    int r, c;
    float w;
    if (idx < E) {
        if (is64) {
            const long long* p64 = (const long long*)ei_raw;
            r = (int)p64[idx];
            c = (int)p64[(size_t)E + idx];
        } else {
            const int* p32 = (const int*)ei_raw;
            r = p32[idx];
            c = p32[(size_t)E + idx];
        }
        w = ew[idx];
    } else {
        r = c = idx - E;
        w = 1.0f;
    }
    float nv = rsqrtf(g_deg[r]) * w * rsqrtf(g_deg[c]);
    int pos = g_rowptr[c] + atomicAdd(&g_cursor[c], 1);
    g_edge[pos] = make_int2(r, __float_as_int(nv));
}

// ------------------- TF32 helpers -------------------
__device__ __forceinline__ float to_tf32(float x) {
    uint32_t o;
    asm("cvt.rna.tf32.f32 %0, %1;" : "=r"(o) : "f"(x));
    return __uint_as_float(o);
}

__device__ __forceinline__ void mma_tf32(float& c0, float& c1, float& c2, float& c3,
                                         uint32_t a0, uint32_t a1, uint32_t a2, uint32_t a3,
                                         uint32_t b0, uint32_t b1) {
    asm volatile(
        "mma.sync.aligned.m16n8k8.row.col.f32.tf32.tf32.f32 "
        "{%0,%1,%2,%3}, {%4,%5,%6,%7}, {%8,%9}, {%0,%1,%2,%3};"
        : "+f"(c0), "+f"(c1), "+f"(c2), "+f"(c3)
        : "r"(a0), "r"(a1), "r"(a2), "r"(a3), "r"(b0), "r"(b1));
}

// ------------------- TF32 tensor GEMM: g_h1[M,128] = A[M,128] @ W[128,128] ----------
// 128x128 block tile, 8 warps; warp owns 16 rows x 128 cols (16 n-tiles of m16n8k8).
// A tile smem [row][k] stride 36, W tile [k][n] stride 136 -> conflict-free LDS.
#define AS_STRIDE 36
#define WS_STRIDE 136
__global__ void __launch_bounds__(256) k_gemm(const float* __restrict__ Aopt,
                                              const float* __restrict__ W, int M) {
    const float* A = Aopt ? Aopt : g_h2;
    float* C = g_h1;
    __shared__ float xs[128][AS_STRIDE];   // A tile: 128 rows x 32 k (tf32)
    __shared__ float ws[32][WS_STRIDE];    // W tile: 32 k x 128 n (tf32)

    int tid = threadIdx.x;
    int wid = tid >> 5;
    int lane = tid & 31;
    int m0 = blockIdx.x * 128;
    int warpRow = wid * 16;               // warp's row base within tile
    int grp = lane >> 2;                  // 0..7
    int sub = lane & 3;                   // 0..3

    float c[16][4];
#pragma unroll
    for (int t = 0; t < 16; t++)
#pragma unroll
        for (int j = 0; j < 4; j++) c[t][j] = 0.0f;

    for (int k0 = 0; k0 < 128; k0 += 32) {
        // load A tile: 128 rows x 32 k = 1024 float4, 4 per thread (tf32-converted)
#pragma unroll
        for (int i = 0; i < 4; i++) {
            int idx = tid + i * 256;      // 0..1023
            int r = idx >> 3;             // row 0..127
            int q = idx & 7;              // float4 index within 32 k
            float4 v = make_float4(0.f, 0.f, 0.f, 0.f);
            if (m0 + r < M)
                v = *(const float4*)(A + (size_t)(m0 + r) * 128 + k0 + q * 4);
            xs[r][q * 4 + 0] = to_tf32(v.x);
            xs[r][q * 4 + 1] = to_tf32(v.y);
            xs[r][q * 4 + 2] = to_tf32(v.z);
            xs[r][q * 4 + 3] = to_tf32(v.w);
        }
        // load W tile: 32 k x 128 n = 1024 float4, 4 per thread (tf32-converted)
#pragma unroll
        for (int i = 0; i < 4; i++) {
            int idx = tid + i * 256;
            int r = idx >> 5;             // k row 0..31
            int q = idx & 31;
            float4 v = *(const float4*)(W + (size_t)(k0 + r) * 128 + q * 4);
            ws[r][q * 4 + 0] = to_tf32(v.x);
            ws[r][q * 4 + 1] = to_tf32(v.y);
            ws[r][q * 4 + 2] = to_tf32(v.z);
            ws[r][q * 4 + 3] = to_tf32(v.w);
        }
        __syncthreads();

#pragma unroll
        for (int kk = 0; kk < 4; kk++) {  // k step of 8 within the 32-chunk
            int kb = kk * 8;
            // A fragment (16x8): rows warpRow+grp(+8), cols kb+sub(+4)
            uint32_t a0 = __float_as_uint(xs[warpRow + grp][kb + sub]);
            uint32_t a1 = __float_as_uint(xs[warpRow + grp + 8][kb + sub]);
            uint32_t a2 = __float_as_uint(xs[warpRow + grp][kb + sub + 4]);
            uint32_t a3 = __float_as_uint(xs[warpRow + grp + 8][kb + sub + 4]);
#pragma unroll
            for (int nt = 0; nt < 16; nt++) {
                // B fragment (8x8): k rows kb+sub(+4), n col nt*8+grp
                uint32_t b0 = __float_as_uint(ws[kb + sub][nt * 8 + grp]);
                uint32_t b1 = __float_as_uint(ws[kb + sub + 4][nt * 8 + grp]);
                mma_tf32(c[nt][0], c[nt][1], c[nt][2], c[nt][3], a0, a1, a2, a3, b0, b1);
            }
        }
        __syncthreads();
    }

    // epilogue: c0/c1 at (row=grp, col=2*sub(+1)), c2/c3 at row=grp+8
    int gr0 = m0 + warpRow + grp;
    int gr1 = gr0 + 8;
#pragma unroll
    for (int nt = 0; nt < 16; nt++) {
        int cb = nt * 8 + 2 * sub;
        if (gr0 < M) *(float2*)(C + (size_t)gr0 * 128 + cb) = make_float2(c[nt][0], c[nt][1]);
        if (gr1 < M) *(float2*)(C + (size_t)gr1 * 128 + cb) = make_float2(c[nt][2], c[nt][3]);
    }
}

// ------------------- SpMM: out[c,:] = sum val*g_h1[src,:] + bias (+relu) ------------
__global__ void __launch_bounds__(256) k_spmm(const float* __restrict__ bias,
                                              float* outOpt, int N, int doRelu) {
    const float4* h = (const float4*)g_h1;
    float* out = outOpt ? outOpt : g_h2;
    int warp = (blockIdx.x * blockDim.x + threadIdx.x) >> 5;
    int lane = threadIdx.x & 31;
    if (warp >= N) return;
    int beg = g_rowptr[warp];
    int end = g_rowptr[warp + 1];

    float4 acc = ((const float4*)bias)[lane];
    int e = beg;

    if ((e & 1) && e < end) {
        int2 p = g_edge[e];
        float4 hv = h[(size_t)p.x * 32 + lane];
        float v = __int_as_float(p.y);
        acc.x += v * hv.x; acc.y += v * hv.y; acc.z += v * hv.z; acc.w += v * hv.w;
        e++;
    }

    for (; e + 8 <= end; e += 8) {
        int4 q0 = *(const int4*)&g_edge[e + 0];
        int4 q1 = *(const int4*)&g_edge[e + 2];
        int4 q2 = *(const int4*)&g_edge[e + 4];
        int4 q3 = *(const int4*)&g_edge[e + 6];
        float4 h0 = h[(size_t)q0.x * 32 + lane];
        float4 h1 = h[(size_t)q0.z * 32 + lane];
        float4 h2 = h[(size_t)q1.x * 32 + lane];
        float4 h3 = h[(size_t)q1.z * 32 + lane];
        float4 h4 = h[(size_t)q2.x * 32 + lane];
        float4 h5 = h[(size_t)q2.z * 32 + lane];
        float4 h6 = h[(size_t)q3.x * 32 + lane];
        float4 h7 = h[(size_t)q3.z * 32 + lane];
        float v0 = __int_as_float(q0.y), v1 = __int_as_float(q0.w);
        float v2 = __int_as_float(q1.y), v3 = __int_as_float(q1.w);
        float v4 = __int_as_float(q2.y), v5 = __int_as_float(q2.w);
        float v6 = __int_as_float(q3.y), v7 = __int_as_float(q3.w);
        acc.x += v0 * h0.x; acc.y += v0 * h0.y; acc.z += v0 * h0.z; acc.w += v0 * h0.w;
        acc.x += v1 * h1.x; acc.y += v1 * h1.y; acc.z += v1 * h1.z; acc.w += v1 * h1.w;
        acc.x += v2 * h2.x; acc.y += v2 * h2.y; acc.z += v2 * h2.z; acc.w += v2 * h2.w;
        acc.x += v3 * h3.x; acc.y += v3 * h3.y; acc.z += v3 * h3.z; acc.w += v3 * h3.w;
        acc.x += v4 * h4.x; acc.y += v4 * h4.y; acc.z += v4 * h4.z; acc.w += v4 * h4.w;
        acc.x += v5 * h5.x; acc.y += v5 * h5.y; acc.z += v5 * h5.z; acc.w += v5 * h5.w;
        acc.x += v6 * h6.x; acc.y += v6 * h6.y; acc.z += v6 * h6.z; acc.w += v6 * h6.w;
        acc.x += v7 * h7.x; acc.y += v7 * h7.y; acc.z += v7 * h7.z; acc.w += v7 * h7.w;
    }

    for (; e + 2 <= end; e += 2) {
        int4 q0 = *(const int4*)&g_edge[e];
        float4 h0 = h[(size_t)q0.x * 32 + lane];
        float4 h1 = h[(size_t)q0.z * 32 + lane];
        float v0 = __int_as_float(q0.y), v1 = __int_as_float(q0.w);
        acc.x += v0 * h0.x; acc.y += v0 * h0.y; acc.z += v0 * h0.z; acc.w += v0 * h0.w;
        acc.x += v1 * h1.x; acc.y += v1 * h1.y; acc.z += v1 * h1.z; acc.w += v1 * h1.w;
    }
    if (e < end) {
        int2 p = g_edge[e];
        float4 hv = h[(size_t)p.x * 32 + lane];
        float v = __int_as_float(p.y);
        acc.x += v * hv.x; acc.y += v * hv.y; acc.z += v * hv.z; acc.w += v * hv.w;
    }

    if (doRelu) {
        acc.x = fmaxf(acc.x, 0.f);
        acc.y = fmaxf(acc.y, 0.f);
        acc.z = fmaxf(acc.z, 0.f);
        acc.w = fmaxf(acc.w, 0.f);
    }
    *(float4*)(out + (size_t)warp * 128 + lane * 4) = acc;
}

// ------------------- launch -------------------
// Launch #4 = TF32 tensor gemm: ncu verifies tensor-pipe activation.
extern "C" void kernel_launch(void* const* d_in, const int* in_sizes, int n_in,
                              void* d_out, int out_size) {
    const float* x  = (const float*)d_in[0];
    const void*  ei = (const void*)d_in[1];
    const float* ew = (const float*)d_in[2];
    const float* W1 = (const float*)d_in[3];
    const float* b1 = (const float*)d_in[4];
    const float* W2 = (const float*)d_in[5];
    const float* b2 = (const float*)d_in[6];
    float* out = (float*)d_out;

    const int E = in_sizes[2];          // 3200000
    const int N = in_sizes[0] / FDIM;   // 100000
    const int T = E + N;

    int gemmGrid = (N + 127) / 128;
    int spmmGrid = (N * 32 + 255) / 256;

    k_init<<<(N + 255) / 256, 256>>>(N);                    // #1
    k_degcount<<<(E + 255) / 256, 256>>>(ei, ew, E, N);     // #2
    k_scan<<<1, SCAN_THREADS>>>(N, T);                      // #3
    k_gemm<<<gemmGrid, 256>>>(x, W1, N);                    // #4  <- ncu capture
    k_scatter<<<(T + 255) / 256, 256>>>(ei, ew, E, N);      // #5

    k_spmm<<<spmmGrid, 256>>>(b1, nullptr, N, 1);           // #6  g_h1 -> g_h2
    k_gemm<<<gemmGrid, 256>>>(nullptr, W2, N);              // #7  g_h2 -> g_h1
    k_spmm<<<spmmGrid, 256>>>(b2, out, N, 0);               // #8  g_h1 -> out
}

// round 9
// speedup vs baseline: 178.4552x; 1.2179x over previous
#include <cuda_runtime.h>
#include <cuda_fp16.h>
#include <stdint.h>

#define MAXN 100000
#define MAXE 3200000
#define MAXT (MAXE + MAXN)
#define FDIM 128
#define SCAN_THREADS 1024

// ------------------- device scratch -------------------
// NOTE: these symbols must ONLY be referenced from device code. Passing them
// as kernel args from host yields the host shadow symbol, which GB300's ATS
// serves from Grace DRAM at ~200 GB/s (the R2-R5 17.9ms bug).
__device__ __align__(16) float g_deg[MAXN];
__device__ int   g_count[MAXN];
__device__ int   g_rowptr[MAXN + 1];
__device__ int   g_cursor[MAXN];
__device__ __align__(16) int2 g_edge[MAXT];   // {src, __float_as_int(norm)}
__device__ __align__(16) __half g_hf[(size_t)MAXN * FDIM];  // gemm out (fp16 gather src)
__device__ __align__(16) float  g_h2[(size_t)MAXN * FDIM];  // spmm1 out (fp32)

// ------------------- dtype sniff helper (int64 vs int32 edge_index) -------------------
__device__ __forceinline__ int sniff_is64(const void* ei_raw, int N) {
    const long long* p64 = (const long long*)ei_raw;
    int ok = 1;
#pragma unroll
    for (int i = 0; i < 4; i++) {
        long long v = p64[i];
        if (v < 0 || v >= (long long)N) ok = 0;
    }
    return ok;
}

// ------------------- init -------------------
__global__ void k_init(int N) {
    int i = blockIdx.x * blockDim.x + threadIdx.x;
    if (i < N) {
        g_count[i] = 1;      // self loop
        g_deg[i] = 1.0f;     // self loop weight
        g_cursor[i] = 0;
    }
}

// ------------------- degree/count atomics over col -------------------
__global__ void k_degcount(const void* __restrict__ ei_raw,
                           const float* __restrict__ ew, int E, int N) {
    __shared__ int is64;
    if (threadIdx.x == 0) is64 = sniff_is64(ei_raw, N);
    __syncthreads();
    int e = blockIdx.x * blockDim.x + threadIdx.x;
    if (e >= E) return;
    int c;
    if (is64) c = (int)((const long long*)ei_raw)[(size_t)E + e];
    else      c = ((const int*)ei_raw)[(size_t)E + e];
    atomicAdd(&g_deg[c], ew[e]);
    atomicAdd(&g_count[c], 1);
}

// ------------------- single-block exclusive scan of g_count -> g_rowptr -------------------
__global__ void k_scan(int N, int total) {
    __shared__ int warpoff[32];
    __shared__ int s_running;
    int t = threadIdx.x;
    int wid = t >> 5, lid = t & 31;
    if (t == 0) s_running = 0;
    __syncthreads();
    int nchunk = (N + SCAN_THREADS - 1) / SCAN_THREADS;
    for (int ch = 0; ch < nchunk; ch++) {
        int i = ch * SCAN_THREADS + t;
        int v = (i < N) ? g_count[i] : 0;
        int s = v;
#pragma unroll
        for (int o = 1; o < 32; o <<= 1) {
            int u = __shfl_up_sync(0xFFFFFFFFu, s, o);
            if (lid >= o) s += u;
        }
        if (lid == 31) warpoff[wid] = s;
        __syncthreads();
        if (t < 32) {
            int w = warpoff[t];
            int sw = w;
#pragma unroll
            for (int o = 1; o < 32; o <<= 1) {
                int u = __shfl_up_sync(0xFFFFFFFFu, sw, o);
                if (t >= o) sw += u;
            }
            warpoff[t] = sw - w;
        }
        __syncthreads();
        int excl = (s - v) + warpoff[wid] + s_running;
        if (i < N) g_rowptr[i] = excl;
        __syncthreads();
        if (t == SCAN_THREADS - 1) s_running = excl + v;
        __syncthreads();
    }
    if (t == 0) g_rowptr[N] = total;
}

// ------------------- scatter into CSR (decode + norm fused) -------------------
__global__ void k_scatter(const void* __restrict__ ei_raw,
                          const float* __restrict__ ew, int E, int N) {
    __shared__ int is64;
    if (threadIdx.x == 0) is64 = sniff_is64(ei_raw, N);
    __syncthreads();
    int idx = blockIdx.x * blockDim.x + threadIdx.x;
    int total = E + N;
    if (idx >= total) return;
    int r, c;
    float w;
    if (idx < E) {
        if (is64) {
            const long long* p64 = (const long long*)ei_raw;
            r = (int)p64[idx];
            c = (int)p64[(size_t)E + idx];
        } else {
            const int* p32 = (const int*)ei_raw;
            r = p32[idx];
            c = p32[(size_t)E + idx];
        }
        w = ew[idx];
    } else {
        r = c = idx - E;
        w = 1.0f;
    }
    float nv = rsqrtf(g_deg[r]) * w * rsqrtf(g_deg[c]);
    int pos = g_rowptr[c] + atomicAdd(&g_cursor[c], 1);
    g_edge[pos] = make_int2(r, __float_as_int(nv));
}

// ------------------- TF32 helpers -------------------
// RNA-round fp32 bits to tf32: +half-ulp of the 13 dropped bits. (Truncation
// would give a systematic -2^-10 bias that accumulates over K=128 -> ~1e-3.)
__device__ __forceinline__ uint32_t rna_tf32(float x) {
    return __float_as_uint(x) + 0x1000u;
}

__device__ __forceinline__ void mma_tf32(float& c0, float& c1, float& c2, float& c3,
                                         uint32_t a0, uint32_t a1, uint32_t a2, uint32_t a3,
                                         uint32_t b0, uint32_t b1) {
    asm volatile(
        "mma.sync.aligned.m16n8k8.row.col.f32.tf32.tf32.f32 "
        "{%0,%1,%2,%3}, {%4,%5,%6,%7}, {%8,%9}, {%0,%1,%2,%3};"
        : "+f"(c0), "+f"(c1), "+f"(c2), "+f"(c3)
        : "r"(a0), "r"(a1), "r"(a2), "r"(a3), "r"(b0), "r"(b1));
}

__device__ __forceinline__ void cp_async16(void* smem_dst, const void* gsrc, int bytes) {
    uint32_t d = (uint32_t)__cvta_generic_to_shared(smem_dst);
    asm volatile("cp.async.cg.shared.global [%0], [%1], 16, %2;"
                 :: "r"(d), "l"(gsrc), "r"(bytes));
}

// ------------------- TF32 tensor GEMM: g_hf[M,128] = A[M,128] @ W[128,128] ----------
// 128x128 block tile, 8 warps in 4x2; warp tile 32 rows x 64 cols.
// cp.async double buffer, k-chunks of 16. Output fp16 (gather source for spmm).
#define AS 20    // A tile row stride (16 k + 4 pad) -> conflict-free frag LDS
#define WS 136   // W tile row stride
__global__ void __launch_bounds__(256) k_gemm(const float* __restrict__ Aopt,
                                              const float* __restrict__ W, int M) {
    const float* A = Aopt ? Aopt : g_h2;
    __half* C = g_hf;
    __shared__ float xs[2][128 * AS];   // 2*128*20*4 = 20480 B
    __shared__ float ws[2][16 * WS];    // 2*16*136*4 = 17408 B

    int tid = threadIdx.x;
    int wid = tid >> 5;
    int lane = tid & 31;
    int grp = lane >> 2;               // 0..7
    int sub = lane & 3;                // 0..3
    int m0 = blockIdx.x * 128;
    int wr = (wid >> 1) * 32;          // warp row base (0,32,64,96)
    int wc = (wid & 1) * 64;           // warp col base (0,64)

    float c[2][8][4];
#pragma unroll
    for (int f = 0; f < 2; f++)
#pragma unroll
        for (int nt = 0; nt < 8; nt++)
#pragma unroll
            for (int j = 0; j < 4; j++) c[f][nt][j] = 0.0f;

    // ---- async tile loaders: chunk = 16 k-columns ----
    // A: 128 rows x 16 k = 512 float4 -> 2 per thread
    // W: 16 rows x 128 n = 512 float4 -> 2 per thread
    auto loadA = [&](int k0, int buf) {
#pragma unroll
        for (int i = 0; i < 2; i++) {
            int idx = tid + i * 256;       // 0..511
            int r = idx >> 2;              // row 0..127
            int q = idx & 3;               // k-quad 0..3
            int bytes = (m0 + r < M) ? 16 : 0;
            cp_async16(&xs[buf][r * AS + q * 4],
                       A + (size_t)(m0 + r) * 128 + k0 + q * 4, bytes);
        }
    };
    auto loadW = [&](int k0, int buf) {
#pragma unroll
        for (int i = 0; i < 2; i++) {
            int idx = tid + i * 256;
            int r = idx >> 5;              // k row 0..15
            int q = idx & 31;
            cp_async16(&ws[buf][r * WS + q * 4],
                       W + (size_t)(k0 + r) * 128 + q * 4, 16);
        }
    };

    loadA(0, 0); loadW(0, 0);
    asm volatile("cp.async.commit_group;");

#pragma unroll
    for (int ch = 0; ch < 8; ch++) {
        int buf = ch & 1;
        if (ch < 7) {
            loadA((ch + 1) * 16, buf ^ 1);
            loadW((ch + 1) * 16, buf ^ 1);
            asm volatile("cp.async.commit_group;");
            asm volatile("cp.async.wait_group 1;");
        } else {
            asm volatile("cp.async.wait_group 0;");
        }
        __syncthreads();

#pragma unroll
        for (int kk = 0; kk < 2; kk++) {
            int kb = kk * 8;
            uint32_t a[2][4];
#pragma unroll
            for (int f = 0; f < 2; f++) {
                int rb = wr + f * 16;
                a[f][0] = rna_tf32(xs[buf][(rb + grp) * AS + kb + sub]);
                a[f][1] = rna_tf32(xs[buf][(rb + grp + 8) * AS + kb + sub]);
                a[f][2] = rna_tf32(xs[buf][(rb + grp) * AS + kb + sub + 4]);
                a[f][3] = rna_tf32(xs[buf][(rb + grp + 8) * AS + kb + sub + 4]);
            }
#pragma unroll
            for (int nt = 0; nt < 8; nt++) {
                uint32_t b0 = rna_tf32(ws[buf][(kb + sub) * WS + wc + nt * 8 + grp]);
                uint32_t b1 = rna_tf32(ws[buf][(kb + sub + 4) * WS + wc + nt * 8 + grp]);
                mma_tf32(c[0][nt][0], c[0][nt][1], c[0][nt][2], c[0][nt][3],
                         a[0][0], a[0][1], a[0][2], a[0][3], b0, b1);
                mma_tf32(c[1][nt][0], c[1][nt][1], c[1][nt][2], c[1][nt][3],
                         a[1][0], a[1][1], a[1][2], a[1][3], b0, b1);
            }
        }
        __syncthreads();   // all reads of buf done before it is refilled
    }

    // epilogue: fp16. frag rows: grp, grp+8 (c01 / c23), frag groups at +0/+16.
#pragma unroll
    for (int f = 0; f < 2; f++) {
#pragma unroll
        for (int nt = 0; nt < 8; nt++) {
            int cb = wc + nt * 8 + 2 * sub;
            int r0 = m0 + wr + f * 16 + grp;
            int r1 = r0 + 8;
            if (r0 < M)
                *(half2*)(C + (size_t)r0 * 128 + cb) =
                    __floats2half2_rn(c[f][nt][0], c[f][nt][1]);
            if (r1 < M)
                *(half2*)(C + (size_t)r1 * 128 + cb) =
                    __floats2half2_rn(c[f][nt][2], c[f][nt][3]);
        }
    }
}

// ------------------- SpMM: out[c,:] = sum val*g_hf[src,:] + bias (+relu) ------------
// Warp per node; lane owns 4 cols = one uint2 (2x half2, 8B). fp32 accumulate.
__global__ void __launch_bounds__(256) k_spmm(const float* __restrict__ bias,
                                              float* outOpt, int N, int doRelu) {
    const uint2* h = (const uint2*)g_hf;   // row = src*32 uint2; lane offset
    float* out = outOpt ? outOpt : g_h2;
    int warp = (blockIdx.x * blockDim.x + threadIdx.x) >> 5;
    int lane = threadIdx.x & 31;
    if (warp >= N) return;
    int beg = g_rowptr[warp];
    int end = g_rowptr[warp + 1];

    float4 acc = ((const float4*)bias)[lane];
    int e = beg;

#define GATHER_FMA(P, V)                                            \
    do {                                                            \
        float2 f0 = __half22float2(*(const half2*)&(P).x);          \
        float2 f1 = __half22float2(*(const half2*)&(P).y);          \
        acc.x += (V) * f0.x; acc.y += (V) * f0.y;                   \
        acc.z += (V) * f1.x; acc.w += (V) * f1.y;                   \
    } while (0)

    if ((e & 1) && e < end) {
        int2 p = g_edge[e];
        uint2 hv = h[(size_t)p.x * 32 + lane];
        GATHER_FMA(hv, __int_as_float(p.y));
        e++;
    }

    for (; e + 8 <= end; e += 8) {
        int4 q0 = *(const int4*)&g_edge[e + 0];
        int4 q1 = *(const int4*)&g_edge[e + 2];
        int4 q2 = *(const int4*)&g_edge[e + 4];
        int4 q3 = *(const int4*)&g_edge[e + 6];
        uint2 h0 = h[(size_t)q0.x * 32 + lane];
        uint2 h1 = h[(size_t)q0.z * 32 + lane];
        uint2 h2 = h[(size_t)q1.x * 32 + lane];
        uint2 h3 = h[(size_t)q1.z * 32 + lane];
        uint2 h4 = h[(size_t)q2.x * 32 + lane];
        uint2 h5 = h[(size_t)q2.z * 32 + lane];
        uint2 h6 = h[(size_t)q3.x * 32 + lane];
        uint2 h7 = h[(size_t)q3.z * 32 + lane];
        GATHER_FMA(h0, __int_as_float(q0.y));
        GATHER_FMA(h1, __int_as_float(q0.w));
        GATHER_FMA(h2, __int_as_float(q1.y));
        GATHER_FMA(h3, __int_as_float(q1.w));
        GATHER_FMA(h4, __int_as_float(q2.y));
        GATHER_FMA(h5, __int_as_float(q2.w));
        GATHER_FMA(h6, __int_as_float(q3.y));
        GATHER_FMA(h7, __int_as_float(q3.w));
    }

    for (; e + 2 <= end; e += 2) {
        int4 q0 = *(const int4*)&g_edge[e];
        uint2 h0 = h[(size_t)q0.x * 32 + lane];
        uint2 h1 = h[(size_t)q0.z * 32 + lane];
        GATHER_FMA(h0, __int_as_float(q0.y));
        GATHER_FMA(h1, __int_as_float(q0.w));
    }
    if (e < end) {
        int2 p = g_edge[e];
        uint2 hv = h[(size_t)p.x * 32 + lane];
        GATHER_FMA(hv, __int_as_float(p.y));
    }
#undef GATHER_FMA

    if (doRelu) {
        acc.x = fmaxf(acc.x, 0.f);
        acc.y = fmaxf(acc.y, 0.f);
        acc.z = fmaxf(acc.z, 0.f);
        acc.w = fmaxf(acc.w, 0.f);
    }
    *(float4*)(out + (size_t)warp * 128 + lane * 4) = acc;
}

// ------------------- launch -------------------
// Launch #4 = gemm1: ncu verifies the cp.async pipeline prediction.
extern "C" void kernel_launch(void* const* d_in, const int* in_sizes, int n_in,
                              void* d_out, int out_size) {
    const float* x  = (const float*)d_in[0];
    const void*  ei = (const void*)d_in[1];
    const float* ew = (const float*)d_in[2];
    const float* W1 = (const float*)d_in[3];
    const float* b1 = (const float*)d_in[4];
    const float* W2 = (const float*)d_in[5];
    const float* b2 = (const float*)d_in[6];
    float* out = (float*)d_out;

    const int E = in_sizes[2];          // 3200000
    const int N = in_sizes[0] / FDIM;   // 100000
    const int T = E + N;

    int gemmGrid = (N + 127) / 128;
    int spmmGrid = (N * 32 + 255) / 256;

    k_init<<<(N + 255) / 256, 256>>>(N);                    // #1
    k_degcount<<<(E + 255) / 256, 256>>>(ei, ew, E, N);     // #2
    k_scan<<<1, SCAN_THREADS>>>(N, T);                      // #3
    k_gemm<<<gemmGrid, 256>>>(x, W1, N);                    // #4  <- ncu capture
    k_scatter<<<(T + 255) / 256, 256>>>(ei, ew, E, N);      // #5

    k_spmm<<<spmmGrid, 256>>>(b1, nullptr, N, 1);           // #6  g_hf -> g_h2
    k_gemm<<<gemmGrid, 256>>>(nullptr, W2, N);              // #7  g_h2 -> g_hf
    k_spmm<<<spmmGrid, 256>>>(b2, out, N, 0);               // #8  g_hf -> out
}

// round 11
// speedup vs baseline: 214.6897x; 1.2030x over previous
#include <cuda_runtime.h>
#include <cuda_fp16.h>
#include <stdint.h>

#define MAXN 100000
#define MAXE 3200000
#define MAXT (MAXE + MAXN)
#define FDIM 128
#define SCAN_CHUNK 1024
#define MAX_SCAN_BLOCKS 128  // ceil(100000/1024)=98

// ------------------- device scratch -------------------
// NOTE: these symbols must ONLY be referenced from device code. Passing them
// as kernel args from host yields the host shadow symbol, which GB300's ATS
// serves from Grace DRAM at ~200 GB/s (the R2-R5 17.9ms bug).
__device__ __align__(16) float g_deg[MAXN];
__device__ int   g_count[MAXN];
__device__ int   g_rowptr[MAXN + 1];
__device__ int   g_cursor[MAXN];
__device__ int   g_partial[MAX_SCAN_BLOCKS];
__device__ int   g_blockoff[MAX_SCAN_BLOCKS];
__device__ __align__(16) int2 g_edge[MAXT];   // {src, __float_as_int(norm)}
__device__ __align__(16) __half g_hf[(size_t)MAXN * FDIM];  // gemm out (fp16 gather src)
__device__ __align__(16) float  g_h2[(size_t)MAXN * FDIM];  // spmm1 out (fp32)

// ------------------- dtype sniff helper (int64 vs int32 edge_index) -------------------
__device__ __forceinline__ int sniff_is64(const void* ei_raw, int N) {
    const long long* p64 = (const long long*)ei_raw;
    int ok = 1;
#pragma unroll
    for (int i = 0; i < 4; i++) {
        long long v = p64[i];
        if (v < 0 || v >= (long long)N) ok = 0;
    }
    return ok;
}

// ------------------- init -------------------
__global__ void k_init(int N) {
    int i = blockIdx.x * blockDim.x + threadIdx.x;
    if (i < N) {
        g_count[i] = 1;      // self loop
        g_deg[i] = 1.0f;     // self loop weight
        g_cursor[i] = 0;
    }
}

// ------------------- degree/count atomics over col -------------------
__global__ void k_degcount(const void* __restrict__ ei_raw,
                           const float* __restrict__ ew, int E, int N) {
    __shared__ int is64;
    if (threadIdx.x == 0) is64 = sniff_is64(ei_raw, N);
    __syncthreads();
    int e = blockIdx.x * blockDim.x + threadIdx.x;
    if (e >= E) return;
    int c;
    if (is64) c = (int)((const long long*)ei_raw)[(size_t)E + e];
    else      c = ((const int*)ei_raw)[(size_t)E + e];
    atomicAdd(&g_deg[c], ew[e]);
    atomicAdd(&g_count[c], 1);
}

// ------------------- scan pass 1: per-block exclusive scan of counts -------------------
__global__ void k_scan1(int N) {
    __shared__ int sm[256];
    int t = threadIdx.x;               // 256 threads, 4 elems each -> 1024 per block
    int base = blockIdx.x * SCAN_CHUNK + t * 4;
    int c0 = (base + 0 < N) ? g_count[base + 0] : 0;
    int c1 = (base + 1 < N) ? g_count[base + 1] : 0;
    int c2 = (base + 2 < N) ? g_count[base + 2] : 0;
    int c3 = (base + 3 < N) ? g_count[base + 3] : 0;
    int tsum = c0 + c1 + c2 + c3;
    sm[t] = tsum;
    __syncthreads();
    for (int off = 1; off < 256; off <<= 1) {
        int v = (t >= off) ? sm[t - off] : 0;
        __syncthreads();
        sm[t] += v;
        __syncthreads();
    }
    int pre = sm[t] - tsum;
    if (base + 0 < N) g_rowptr[base + 0] = pre;
    if (base + 1 < N) g_rowptr[base + 1] = pre + c0;
    if (base + 2 < N) g_rowptr[base + 2] = pre + c0 + c1;
    if (base + 3 < N) g_rowptr[base + 3] = pre + c0 + c1 + c2;
    if (t == 255) g_partial[blockIdx.x] = sm[255];
}

// ------------------- scan pass 2: scan block partials (single block) -------------------
__global__ void k_scan2(int nb, int N, int total) {
    __shared__ int sm[MAX_SCAN_BLOCKS];
    int t = threadIdx.x;               // blockDim = MAX_SCAN_BLOCKS
    int v = (t < nb) ? g_partial[t] : 0;
    sm[t] = v;
    __syncthreads();
    for (int off = 1; off < MAX_SCAN_BLOCKS; off <<= 1) {
        int u = (t >= off) ? sm[t - off] : 0;
        __syncthreads();
        sm[t] += u;
        __syncthreads();
    }
    if (t < nb) g_blockoff[t] = sm[t] - v;
    if (t == 0) g_rowptr[N] = total;
}

// ------------------- scan pass 3: add block offsets -------------------
__global__ void k_scan3(int N) {
    int i = blockIdx.x * blockDim.x + threadIdx.x;
    if (i < N) g_rowptr[i] += g_blockoff[i >> 10];
}

// ------------------- scatter into CSR (decode + norm fused) -------------------
__global__ void k_scatter(const void* __restrict__ ei_raw,
                          const float* __restrict__ ew, int E, int N) {
    __shared__ int is64;
    if (threadIdx.x == 0) is64 = sniff_is64(ei_raw, N);
    __syncthreads();
    int idx = blockIdx.x * blockDim.x + threadIdx.x;
    int total = E + N;
    if (idx >= total) return;
    int r, c;
    float w;
    if (idx < E) {
        if (is64) {
            const long long* p64 = (const long long*)ei_raw;
            r = (int)p64[idx];
            c = (int)p64[(size_t)E + idx];
        } else {
            const int* p32 = (const int*)ei_raw;
            r = p32[idx];
            c = p32[(size_t)E + idx];
        }
        w = ew[idx];
    } else {
        r = c = idx - E;
        w = 1.0f;
    }
    float nv = rsqrtf(g_deg[r]) * w * rsqrtf(g_deg[c]);
    int pos = g_rowptr[c] + atomicAdd(&g_cursor[c], 1);
    g_edge[pos] = make_int2(r, __float_as_int(nv));
}

// ------------------- TF32 helpers -------------------
// RNA-round fp32 bits to tf32: +half-ulp of the 13 dropped bits. (Truncation
// would give a systematic -2^-10 bias that accumulates over K=128 -> ~1e-3.)
__device__ __forceinline__ uint32_t rna_tf32(float x) {
    return __float_as_uint(x) + 0x1000u;
}

__device__ __forceinline__ void mma_tf32(float& c0, float& c1, float& c2, float& c3,
                                         uint32_t a0, uint32_t a1, uint32_t a2, uint32_t a3,
                                         uint32_t b0, uint32_t b1) {
    asm volatile(
        "mma.sync.aligned.m16n8k8.row.col.f32.tf32.tf32.f32 "
        "{%0,%1,%2,%3}, {%4,%5,%6,%7}, {%8,%9}, {%0,%1,%2,%3};"
        : "+f"(c0), "+f"(c1), "+f"(c2), "+f"(c3)
        : "r"(a0), "r"(a1), "r"(a2), "r"(a3), "r"(b0), "r"(b1));
}

__device__ __forceinline__ void cp_async16(void* smem_dst, const void* gsrc, int bytes) {
    uint32_t d = (uint32_t)__cvta_generic_to_shared(smem_dst);
    asm volatile("cp.async.cg.shared.global [%0], [%1], 16, %2;"
                 :: "r"(d), "l"(gsrc), "r"(bytes));
}

// ------------------- TF32 tensor GEMM: g_hf[M,128] = A[M,128] @ W[128,128] ----------
// 64x128 block tile, 8 warps in 2x4; warp tile 32 rows x 32 cols (32 accum regs ->
// ~4 blocks/SM resident for latency hiding). cp.async double buffer, k-chunks of 16.
#define AS 20    // A tile row stride (16 k + 4 pad)
#define WS 136   // W tile row stride
__global__ void __launch_bounds__(256) k_gemm(const float* __restrict__ Aopt,
                                              const float* __restrict__ W, int M) {
    const float* A = Aopt ? Aopt : g_h2;
    __half* C = g_hf;
    __shared__ float xs[2][64 * AS];    // 2*64*20*4  = 10240 B
    __shared__ float ws[2][16 * WS];    // 2*16*136*4 = 17408 B

    int tid = threadIdx.x;
    int wid = tid >> 5;
    int lane = tid & 31;
    int grp = lane >> 2;               // 0..7
    int sub = lane & 3;                // 0..3
    int m0 = blockIdx.x * 64;
    int wr = (wid >> 2) * 32;          // warp row base (0,32)
    int wc = (wid & 3) * 32;           // warp col base (0,32,64,96)

    float c[2][4][4];                  // f (m16 frag) x nt (n8 tile) x 4
#pragma unroll
    for (int f = 0; f < 2; f++)
#pragma unroll
        for (int nt = 0; nt < 4; nt++)
#pragma unroll
            for (int j = 0; j < 4; j++) c[f][nt][j] = 0.0f;

    // ---- async tile loaders: chunk = 16 k-columns ----
    // A: 64 rows x 16 k = 256 float4 -> 1 per thread
    // W: 16 rows x 128 n = 512 float4 -> 2 per thread
    auto loadA = [&](int k0, int buf) {
        int r = tid >> 2;              // row 0..63
        int q = tid & 3;               // k-quad 0..3
        int bytes = (m0 + r < M) ? 16 : 0;
        cp_async16(&xs[buf][r * AS + q * 4],
                   A + (size_t)(m0 + r) * 128 + k0 + q * 4, bytes);
    };
    auto loadW = [&](int k0, int buf) {
#pragma unroll
        for (int i = 0; i < 2; i++) {
            int idx = tid + i * 256;
            int r = idx >> 5;          // k row 0..15
            int q = idx & 31;
            cp_async16(&ws[buf][r * WS + q * 4],
                       W + (size_t)(k0 + r) * 128 + q * 4, 16);
        }
    };

    loadA(0, 0); loadW(0, 0);
    asm volatile("cp.async.commit_group;");

#pragma unroll
    for (int ch = 0; ch < 8; ch++) {
        int buf = ch & 1;
        if (ch < 7) {
            loadA((ch + 1) * 16, buf ^ 1);
            loadW((ch + 1) * 16, buf ^ 1);
            asm volatile("cp.async.commit_group;");
            asm volatile("cp.async.wait_group 1;");
        } else {
            asm volatile("cp.async.wait_group 0;");
        }
        __syncthreads();

#pragma unroll
        for (int kk = 0; kk < 2; kk++) {
            int kb = kk * 8;
            uint32_t a[2][4];
#pragma unroll
            for (int f = 0; f < 2; f++) {
                int rb = wr + f * 16;
                a[f][0] = rna_tf32(xs[buf][(rb + grp) * AS + kb + sub]);
                a[f][1] = rna_tf32(xs[buf][(rb + grp + 8) * AS + kb + sub]);
                a[f][2] = rna_tf32(xs[buf][(rb + grp) * AS + kb + sub + 4]);
                a[f][3] = rna_tf32(xs[buf][(rb + grp + 8) * AS + kb + sub + 4]);
            }
#pragma unroll
            for (int nt = 0; nt < 4; nt++) {
                uint32_t b0 = rna_tf32(ws[buf][(kb + sub) * WS + wc + nt * 8 + grp]);
                uint32_t b1 = rna_tf32(ws[buf][(kb + sub + 4) * WS + wc + nt * 8 + grp]);
                mma_tf32(c[0][nt][0], c[0][nt][1], c[0][nt][2], c[0][nt][3],
                         a[0][0], a[0][1], a[0][2], a[0][3], b0, b1);
                mma_tf32(c[1][nt][0], c[1][nt][1], c[1][nt][2], c[1][nt][3],
                         a[1][0], a[1][1], a[1][2], a[1][3], b0, b1);
            }
        }
        __syncthreads();   // all reads of buf done before it is refilled
    }

    // epilogue: fp16. frag rows grp/grp+8 within frag f at wr + f*16.
#pragma unroll
    for (int f = 0; f < 2; f++) {
#pragma unroll
        for (int nt = 0; nt < 4; nt++) {
            int cb = wc + nt * 8 + 2 * sub;
            int r0 = m0 + wr + f * 16 + grp;
            int r1 = r0 + 8;
            if (r0 < M)
                *(half2*)(C + (size_t)r0 * 128 + cb) =
                    __floats2half2_rn(c[f][nt][0], c[f][nt][1]);
            if (r1 < M)
                *(half2*)(C + (size_t)r1 * 128 + cb) =
                    __floats2half2_rn(c[f][nt][2], c[f][nt][3]);
        }
    }
}

// ------------------- SpMM: out[c,:] = sum val*g_hf[src,:] + bias (+relu) ------------
// Warp per node; lane owns 4 cols = one uint2 (2x half2, 8B). fp32 accumulate.
__global__ void __launch_bounds__(256) k_spmm(const float* __restrict__ bias,
                                              float* outOpt, int N, int doRelu) {
    const uint2* h = (const uint2*)g_hf;
    float* out = outOpt ? outOpt : g_h2;
    int warp = (blockIdx.x * blockDim.x + threadIdx.x) >> 5;
    int lane = threadIdx.x & 31;
    if (warp >= N) return;
    int beg = g_rowptr[warp];
    int end = g_rowptr[warp + 1];

    float4 acc = ((const float4*)bias)[lane];
    int e = beg;

#define GATHER_FMA(P, V)                                            \
    do {                                                            \
        float2 f0 = __half22float2(*(const half2*)&(P).x);          \
        float2 f1 = __half22float2(*(const half2*)&(P).y);          \
        acc.x += (V) * f0.x; acc.y += (V) * f0.y;                   \
        acc.z += (V) * f1.x; acc.w += (V) * f1.y;                   \
    } while (0)

    if ((e & 1) && e < end) {
        int2 p = g_edge[e];
        uint2 hv = h[(size_t)p.x * 32 + lane];
        GATHER_FMA(hv, __int_as_float(p.y));
        e++;
    }

    for (; e + 8 <= end; e += 8) {
        int4 q0 = *(const int4*)&g_edge[e + 0];
        int4 q1 = *(const int4*)&g_edge[e + 2];
        int4 q2 = *(const int4*)&g_edge[e + 4];
        int4 q3 = *(const int4*)&g_edge[e + 6];
        uint2 h0 = h[(size_t)q0.x * 32 + lane];
        uint2 h1 = h[(size_t)q0.z * 32 + lane];
        uint2 h2 = h[(size_t)q1.x * 32 + lane];
        uint2 h3 = h[(size_t)q1.z * 32 + lane];
        uint2 h4 = h[(size_t)q2.x * 32 + lane];
        uint2 h5 = h[(size_t)q2.z * 32 + lane];
        uint2 h6 = h[(size_t)q3.x * 32 + lane];
        uint2 h7 = h[(size_t)q3.z * 32 + lane];
        GATHER_FMA(h0, __int_as_float(q0.y));
        GATHER_FMA(h1, __int_as_float(q0.w));
        GATHER_FMA(h2, __int_as_float(q1.y));
        GATHER_FMA(h3, __int_as_float(q1.w));
        GATHER_FMA(h4, __int_as_float(q2.y));
        GATHER_FMA(h5, __int_as_float(q2.w));
        GATHER_FMA(h6, __int_as_float(q3.y));
        GATHER_FMA(h7, __int_as_float(q3.w));
    }

    for (; e + 2 <= end; e += 2) {
        int4 q0 = *(const int4*)&g_edge[e];
        uint2 h0 = h[(size_t)q0.x * 32 + lane];
        uint2 h1 = h[(size_t)q0.z * 32 + lane];
        GATHER_FMA(h0, __int_as_float(q0.y));
        GATHER_FMA(h1, __int_as_float(q0.w));
    }
    if (e < end) {
        int2 p = g_edge[e];
        uint2 hv = h[(size_t)p.x * 32 + lane];
        GATHER_FMA(hv, __int_as_float(p.y));
    }
#undef GATHER_FMA

    if (doRelu) {
        acc.x = fmaxf(acc.x, 0.f);
        acc.y = fmaxf(acc.y, 0.f);
        acc.z = fmaxf(acc.z, 0.f);
        acc.w = fmaxf(acc.w, 0.f);
    }
    *(float4*)(out + (size_t)warp * 128 + lane * 4) = acc;
}

// ------------------- launch -------------------
// Launch #4 = gemm1: ncu verifies the occupancy/tensor% prediction.
extern "C" void kernel_launch(void* const* d_in, const int* in_sizes, int n_in,
                              void* d_out, int out_size) {
    const float* x  = (const float*)d_in[0];
    const void*  ei = (const void*)d_in[1];
    const float* ew = (const float*)d_in[2];
    const float* W1 = (const float*)d_in[3];
    const float* b1 = (const float*)d_in[4];
    const float* W2 = (const float*)d_in[5];
    const float* b2 = (const float*)d_in[6];
    float* out = (float*)d_out;

    const int E = in_sizes[2];          // 3200000
    const int N = in_sizes[0] / FDIM;   // 100000
    const int T = E + N;

    int gemmGrid = (N + 63) / 64;
    int spmmGrid = (N * 32 + 255) / 256;
    int nb = (N + SCAN_CHUNK - 1) / SCAN_CHUNK;

    k_init<<<(N + 255) / 256, 256>>>(N);                    // #1
    k_degcount<<<(E + 255) / 256, 256>>>(ei, ew, E, N);     // #2
    k_scan1<<<nb, 256>>>(N);                                // #3
    k_gemm<<<gemmGrid, 256>>>(x, W1, N);                    // #4  <- ncu capture
    k_scan2<<<1, MAX_SCAN_BLOCKS>>>(nb, N, T);              // #5
    k_scan3<<<(N + 255) / 256, 256>>>(N);                   // #6
    k_scatter<<<(T + 255) / 256, 256>>>(ei, ew, E, N);      // #7

    k_spmm<<<spmmGrid, 256>>>(b1, nullptr, N, 1);           // #8  g_hf -> g_h2
    k_gemm<<<gemmGrid, 256>>>(nullptr, W2, N);              // #9  g_h2 -> g_hf
    k_spmm<<<spmmGrid, 256>>>(b2, out, N, 0);               // #10 g_hf -> out
}

// round 12
// speedup vs baseline: 226.9513x; 1.0571x over previous
#include <cuda_runtime.h>
#include <cuda_fp16.h>
#include <stdint.h>

#define MAXN 100000
#define MAXE 3200000
#define MAXT (MAXE + MAXN)
#define FDIM 128
#define SCAN_CHUNK 1024
#define MAX_SCAN_BLOCKS 128  // ceil(100000/1024)=98
#define FIX_SCALE 1048576.0f          // 2^20 fixed-point for weighted degree
#define MASK52 ((1ULL << 52) - 1)

// ------------------- device scratch -------------------
// NOTE: these symbols must ONLY be referenced from device code. Passing them
// as kernel args from host yields the host shadow symbol, which GB300's ATS
// serves from Grace DRAM at ~200 GB/s (the R2-R5 17.9ms bug).
__device__ unsigned long long g_dc[MAXN];     // [count:52..63][deg*2^20:0..51]
__device__ int   g_rowptr[MAXN + 1];
__device__ int   g_cursor[MAXN];
__device__ int   g_partial[MAX_SCAN_BLOCKS];
__device__ int   g_blockoff[MAX_SCAN_BLOCKS];
__device__ __align__(16) int2 g_edge[MAXT];   // {src, __float_as_int(norm)}
__device__ __align__(16) __half g_hf[(size_t)MAXN * FDIM];  // gemm out (fp16 gather src)
__device__ __align__(16) float  g_h2[(size_t)MAXN * FDIM];  // spmm1 out (fp32)

// ------------------- dtype sniff helper (int64 vs int32 edge_index) -------------------
__device__ __forceinline__ int sniff_is64(const void* ei_raw, int N) {
    const long long* p64 = (const long long*)ei_raw;
    int ok = 1;
#pragma unroll
    for (int i = 0; i < 4; i++) {
        long long v = p64[i];
        if (v < 0 || v >= (long long)N) ok = 0;
    }
    return ok;
}

// ------------------- init: self loop -> count=1, deg=1.0 -------------------
__global__ void k_init(int N) {
    int i = blockIdx.x * blockDim.x + threadIdx.x;
    if (i < N) {
        g_dc[i] = (1ULL << 52) | (unsigned long long)(1u << 20);
        g_cursor[i] = 0;
    }
}

// ------------------- degree+count in ONE packed 64-bit atomic per edge ----------
__global__ void k_degcount(const void* __restrict__ ei_raw,
                           const float* __restrict__ ew, int E, int N) {
    __shared__ int is64;
    if (threadIdx.x == 0) is64 = sniff_is64(ei_raw, N);
    __syncthreads();
    int e = blockIdx.x * blockDim.x + threadIdx.x;
    if (e >= E) return;
    int c;
    if (is64) c = (int)((const long long*)ei_raw)[(size_t)E + e];
    else      c = ((const int*)ei_raw)[(size_t)E + e];
    unsigned long long pk =
        (1ULL << 52) | (unsigned long long)__float2uint_rn(ew[e] * FIX_SCALE);
    atomicAdd(&g_dc[c], pk);
}

// ------------------- scan pass 1: per-block exclusive scan of counts -------------------
__global__ void k_scan1(int N) {
    __shared__ int sm[256];
    int t = threadIdx.x;               // 256 threads, 4 elems each -> 1024 per block
    int base = blockIdx.x * SCAN_CHUNK + t * 4;
    int c0 = (base + 0 < N) ? (int)(g_dc[base + 0] >> 52) : 0;
    int c1 = (base + 1 < N) ? (int)(g_dc[base + 1] >> 52) : 0;
    int c2 = (base + 2 < N) ? (int)(g_dc[base + 2] >> 52) : 0;
    int c3 = (base + 3 < N) ? (int)(g_dc[base + 3] >> 52) : 0;
    int tsum = c0 + c1 + c2 + c3;
    sm[t] = tsum;
    __syncthreads();
    for (int off = 1; off < 256; off <<= 1) {
        int v = (t >= off) ? sm[t - off] : 0;
        __syncthreads();
        sm[t] += v;
        __syncthreads();
    }
    int pre = sm[t] - tsum;
    if (base + 0 < N) g_rowptr[base + 0] = pre;
    if (base + 1 < N) g_rowptr[base + 1] = pre + c0;
    if (base + 2 < N) g_rowptr[base + 2] = pre + c0 + c1;
    if (base + 3 < N) g_rowptr[base + 3] = pre + c0 + c1 + c2;
    if (t == 255) g_partial[blockIdx.x] = sm[255];
}

// ------------------- scan pass 2: scan block partials (single block) -------------------
__global__ void k_scan2(int nb, int N, int total) {
    __shared__ int sm[MAX_SCAN_BLOCKS];
    int t = threadIdx.x;               // blockDim = MAX_SCAN_BLOCKS
    int v = (t < nb) ? g_partial[t] : 0;
    sm[t] = v;
    __syncthreads();
    for (int off = 1; off < MAX_SCAN_BLOCKS; off <<= 1) {
        int u = (t >= off) ? sm[t - off] : 0;
        __syncthreads();
        sm[t] += u;
        __syncthreads();
    }
    if (t < nb) g_blockoff[t] = sm[t] - v;
    if (t == 0) g_rowptr[N] = total;
}

// ------------------- scan pass 3: add block offsets -------------------
__global__ void k_scan3(int N) {
    int i = blockIdx.x * blockDim.x + threadIdx.x;
    if (i < N) g_rowptr[i] += g_blockoff[i >> 10];
}

// ------------------- scatter into CSR (decode + norm fused) -------------------
__device__ __forceinline__ float unpack_deg(unsigned long long pk) {
    return (float)(pk & MASK52) * (1.0f / FIX_SCALE);
}

__global__ void k_scatter(const void* __restrict__ ei_raw,
                          const float* __restrict__ ew, int E, int N) {
    __shared__ int is64;
    if (threadIdx.x == 0) is64 = sniff_is64(ei_raw, N);
    __syncthreads();
    int idx = blockIdx.x * blockDim.x + threadIdx.x;
    int total = E + N;
    if (idx >= total) return;
    int r, c;
    float w;
    if (idx < E) {
        if (is64) {
            const long long* p64 = (const long long*)ei_raw;
            r = (int)p64[idx];
            c = (int)p64[(size_t)E + idx];
        } else {
            const int* p32 = (const int*)ei_raw;
            r = p32[idx];
            c = p32[(size_t)E + idx];
        }
        w = ew[idx];
    } else {
        r = c = idx - E;
        w = 1.0f;
    }
    float nv = rsqrtf(unpack_deg(g_dc[r])) * w * rsqrtf(unpack_deg(g_dc[c]));
    int pos = g_rowptr[c] + atomicAdd(&g_cursor[c], 1);
    g_edge[pos] = make_int2(r, __float_as_int(nv));
}

// ------------------- TF32 helpers -------------------
// RNA-round fp32 bits to tf32: +half-ulp of the 13 dropped bits. (Truncation
// would give a systematic -2^-10 bias that accumulates over K=128 -> ~1e-3.)
__device__ __forceinline__ uint32_t rna_tf32(float x) {
    return __float_as_uint(x) + 0x1000u;
}

__device__ __forceinline__ void mma_tf32(float& c0, float& c1, float& c2, float& c3,
                                         uint32_t a0, uint32_t a1, uint32_t a2, uint32_t a3,
                                         uint32_t b0, uint32_t b1) {
    asm volatile(
        "mma.sync.aligned.m16n8k8.row.col.f32.tf32.tf32.f32 "
        "{%0,%1,%2,%3}, {%4,%5,%6,%7}, {%8,%9}, {%0,%1,%2,%3};"
        : "+f"(c0), "+f"(c1), "+f"(c2), "+f"(c3)
        : "r"(a0), "r"(a1), "r"(a2), "r"(a3), "r"(b0), "r"(b1));
}

__device__ __forceinline__ void cp_async16(void* smem_dst, const void* gsrc, int bytes) {
    uint32_t d = (uint32_t)__cvta_generic_to_shared(smem_dst);
    asm volatile("cp.async.cg.shared.global [%0], [%1], 16, %2;"
                 :: "r"(d), "l"(gsrc), "r"(bytes));
}

// ------------------- TF32 tensor GEMM: g_hf[M,128] = A[M,128] @ W[128,128] ----------
// 64x128 block tile, 8 warps in 2x4; warp tile 32x32. 3-stage cp.async pipeline,
// k-chunks of 16, ONE __syncthreads per chunk.
#define AS 20    // A tile row stride (16 k + 4 pad)
#define WS 136   // W tile row stride
__global__ void __launch_bounds__(256) k_gemm(const float* __restrict__ Aopt,
                                              const float* __restrict__ W, int M) {
    const float* A = Aopt ? Aopt : g_h2;
    __half* C = g_hf;
    __shared__ float xs[3][64 * AS];    // 3*64*20*4  = 15360 B
    __shared__ float ws[3][16 * WS];    // 3*16*136*4 = 26112 B

    int tid = threadIdx.x;
    int wid = tid >> 5;
    int lane = tid & 31;
    int grp = lane >> 2;               // 0..7
    int sub = lane & 3;                // 0..3
    int m0 = blockIdx.x * 64;
    int wr = (wid >> 2) * 32;          // warp row base (0,32)
    int wc = (wid & 3) * 32;           // warp col base (0,32,64,96)

    float c[2][4][4];
#pragma unroll
    for (int f = 0; f < 2; f++)
#pragma unroll
        for (int nt = 0; nt < 4; nt++)
#pragma unroll
            for (int j = 0; j < 4; j++) c[f][nt][j] = 0.0f;

    // A: 64 rows x 16 k = 256 float4 -> 1 per thread
    // W: 16 rows x 128 n = 512 float4 -> 2 per thread
    auto loadA = [&](int k0, int buf) {
        int r = tid >> 2;
        int q = tid & 3;
        int bytes = (m0 + r < M) ? 16 : 0;
        cp_async16(&xs[buf][r * AS + q * 4],
                   A + (size_t)(m0 + r) * 128 + k0 + q * 4, bytes);
    };
    auto loadW = [&](int k0, int buf) {
#pragma unroll
        for (int i = 0; i < 2; i++) {
            int idx = tid + i * 256;
            int r = idx >> 5;
            int q = idx & 31;
            cp_async16(&ws[buf][r * WS + q * 4],
                       W + (size_t)(k0 + r) * 128 + q * 4, 16);
        }
    };

    loadA(0, 0);  loadW(0, 0);  asm volatile("cp.async.commit_group;");
    loadA(16, 1); loadW(16, 1); asm volatile("cp.async.commit_group;");

#pragma unroll
    for (int ch = 0; ch < 8; ch++) {
        int buf = ch % 3;
        if (ch < 7) asm volatile("cp.async.wait_group 1;");
        else        asm volatile("cp.async.wait_group 0;");
        __syncthreads();   // chunk ch ready everywhere; all warps done with chunk ch-1
        if (ch + 2 < 8) {
            int nb = (ch + 2) % 3;   // last read in chunk ch-1 -> safe to refill
            loadA((ch + 2) * 16, nb);
            loadW((ch + 2) * 16, nb);
            asm volatile("cp.async.commit_group;");
        }

#pragma unroll
        for (int kk = 0; kk < 2; kk++) {
            int kb = kk * 8;
            uint32_t a[2][4];
#pragma unroll
            for (int f = 0; f < 2; f++) {
                int rb = wr + f * 16;
                a[f][0] = rna_tf32(xs[buf][(rb + grp) * AS + kb + sub]);
                a[f][1] = rna_tf32(xs[buf][(rb + grp + 8) * AS + kb + sub]);
                a[f][2] = rna_tf32(xs[buf][(rb + grp) * AS + kb + sub + 4]);
                a[f][3] = rna_tf32(xs[buf][(rb + grp + 8) * AS + kb + sub + 4]);
            }
#pragma unroll
            for (int nt = 0; nt < 4; nt++) {
                uint32_t b0 = rna_tf32(ws[buf][(kb + sub) * WS + wc + nt * 8 + grp]);
                uint32_t b1 = rna_tf32(ws[buf][(kb + sub + 4) * WS + wc + nt * 8 + grp]);
                mma_tf32(c[0][nt][0], c[0][nt][1], c[0][nt][2], c[0][nt][3],
                         a[0][0], a[0][1], a[0][2], a[0][3], b0, b1);
                mma_tf32(c[1][nt][0], c[1][nt][1], c[1][nt][2], c[1][nt][3],
                         a[1][0], a[1][1], a[1][2], a[1][3], b0, b1);
            }
        }
    }

    // epilogue: fp16
#pragma unroll
    for (int f = 0; f < 2; f++) {
#pragma unroll
        for (int nt = 0; nt < 4; nt++) {
            int cb = wc + nt * 8 + 2 * sub;
            int r0 = m0 + wr + f * 16 + grp;
            int r1 = r0 + 8;
            if (r0 < M)
                *(half2*)(C + (size_t)r0 * 128 + cb) =
                    __floats2half2_rn(c[f][nt][0], c[f][nt][1]);
            if (r1 < M)
                *(half2*)(C + (size_t)r1 * 128 + cb) =
                    __floats2half2_rn(c[f][nt][2], c[f][nt][3]);
        }
    }
}

// ------------------- SpMM: out[c,:] = sum val*g_hf[src,:] + bias (+relu) ------------
__global__ void __launch_bounds__(256) k_spmm(const float* __restrict__ bias,
                                              float* outOpt, int N, int doRelu) {
    const uint2* h = (const uint2*)g_hf;
    float* out = outOpt ? outOpt : g_h2;
    int warp = (blockIdx.x * blockDim.x + threadIdx.x) >> 5;
    int lane = threadIdx.x & 31;
    if (warp >= N) return;
    int beg = g_rowptr[warp];
    int end = g_rowptr[warp + 1];

    float4 acc = ((const float4*)bias)[lane];
    int e = beg;

#define GATHER_FMA(P, V)                                            \
    do {                                                            \
        float2 f0 = __half22float2(*(const half2*)&(P).x);          \
        float2 f1 = __half22float2(*(const half2*)&(P).y);          \
        acc.x += (V) * f0.x; acc.y += (V) * f0.y;                   \
        acc.z += (V) * f1.x; acc.w += (V) * f1.y;                   \
    } while (0)

    if ((e & 1) && e < end) {
        int2 p = g_edge[e];
        uint2 hv = h[(size_t)p.x * 32 + lane];
        GATHER_FMA(hv, __int_as_float(p.y));
        e++;
    }

    for (; e + 8 <= end; e += 8) {
        int4 q0 = *(const int4*)&g_edge[e + 0];
        int4 q1 = *(const int4*)&g_edge[e + 2];
        int4 q2 = *(const int4*)&g_edge[e + 4];
        int4 q3 = *(const int4*)&g_edge[e + 6];
        uint2 h0 = h[(size_t)q0.x * 32 + lane];
        uint2 h1 = h[(size_t)q0.z * 32 + lane];
        uint2 h2 = h[(size_t)q1.x * 32 + lane];
        uint2 h3 = h[(size_t)q1.z * 32 + lane];
        uint2 h4 = h[(size_t)q2.x * 32 + lane];
        uint2 h5 = h[(size_t)q2.z * 32 + lane];
        uint2 h6 = h[(size_t)q3.x * 32 + lane];
        uint2 h7 = h[(size_t)q3.z * 32 + lane];
        GATHER_FMA(h0, __int_as_float(q0.y));
        GATHER_FMA(h1, __int_as_float(q0.w));
        GATHER_FMA(h2, __int_as_float(q1.y));
        GATHER_FMA(h3, __int_as_float(q1.w));
        GATHER_FMA(h4, __int_as_float(q2.y));
        GATHER_FMA(h5, __int_as_float(q2.w));
        GATHER_FMA(h6, __int_as_float(q3.y));
        GATHER_FMA(h7, __int_as_float(q3.w));
    }

    for (; e + 2 <= end; e += 2) {
        int4 q0 = *(const int4*)&g_edge[e];
        uint2 h0 = h[(size_t)q0.x * 32 + lane];
        uint2 h1 = h[(size_t)q0.z * 32 + lane];
        GATHER_FMA(h0, __int_as_float(q0.y));
        GATHER_FMA(h1, __int_as_float(q0.w));
    }
    if (e < end) {
        int2 p = g_edge[e];
        uint2 hv = h[(size_t)p.x * 32 + lane];
        GATHER_FMA(hv, __int_as_float(p.y));
    }
#undef GATHER_FMA

    if (doRelu) {
        acc.x = fmaxf(acc.x, 0.f);
        acc.y = fmaxf(acc.y, 0.f);
        acc.z = fmaxf(acc.z, 0.f);
        acc.w = fmaxf(acc.w, 0.f);
    }
    *(float4*)(out + (size_t)warp * 128 + lane * 4) = acc;
}

// ------------------- launch -------------------
// Launch #4 = gemm1: ncu verifies the 3-stage pipeline prediction.
extern "C" void kernel_launch(void* const* d_in, const int* in_sizes, int n_in,
                              void* d_out, int out_size) {
    const float* x  = (const float*)d_in[0];
    const void*  ei = (const void*)d_in[1];
    const float* ew = (const float*)d_in[2];
    const float* W1 = (const float*)d_in[3];
    const float* b1 = (const float*)d_in[4];
    const float* W2 = (const float*)d_in[5];
    const float* b2 = (const float*)d_in[6];
    float* out = (float*)d_out;

    const int E = in_sizes[2];          // 3200000
    const int N = in_sizes[0] / FDIM;   // 100000
    const int T = E + N;

    int gemmGrid = (N + 63) / 64;
    int spmmGrid = (N * 32 + 255) / 256;
    int nb = (N + SCAN_CHUNK - 1) / SCAN_CHUNK;

    k_init<<<(N + 255) / 256, 256>>>(N);                    // #1
    k_degcount<<<(E + 255) / 256, 256>>>(ei, ew, E, N);     // #2
    k_scan1<<<nb, 256>>>(N);                                // #3
    k_gemm<<<gemmGrid, 256>>>(x, W1, N);                    // #4  <- ncu capture
    k_scan2<<<1, MAX_SCAN_BLOCKS>>>(nb, N, T);              // #5
    k_scan3<<<(N + 255) / 256, 256>>>(N);                   // #6
    k_scatter<<<(T + 255) / 256, 256>>>(ei, ew, E, N);      // #7

    k_spmm<<<spmmGrid, 256>>>(b1, nullptr, N, 1);           // #8  g_hf -> g_h2
    k_gemm<<<gemmGrid, 256>>>(nullptr, W2, N);              // #9  g_h2 -> g_hf
    k_spmm<<<spmmGrid, 256>>>(b2, out, N, 0);               // #10 g_hf -> out
}

// round 13
// speedup vs baseline: 233.8728x; 1.0305x over previous
#include <cuda_runtime.h>
#include <cuda_fp16.h>
#include <stdint.h>

#define MAXN 100000
#define MAXE 3200000
#define MAXT (MAXE + MAXN)
#define FDIM 128
#define SCAN_CHUNK 1024
#define MAX_SCAN_BLOCKS 128  // ceil(100000/1024)=98
#define FIX_SCALE 1048576.0f          // 2^20 fixed-point for weighted degree
#define MASK52 ((1ULL << 52) - 1)

// ------------------- device scratch -------------------
// NOTE: these symbols must ONLY be referenced from device code. Passing them
// as kernel args from host yields the host shadow symbol, which GB300's ATS
// serves from Grace DRAM at ~200 GB/s (the R2-R5 17.9ms bug).
__device__ unsigned long long g_dc[MAXN];     // [count:52..63][deg*2^20:0..51]
__device__ int   g_rowptr[MAXN + 1];
__device__ int   g_cursor[MAXN];
__device__ int   g_partial[MAX_SCAN_BLOCKS];
__device__ int   g_blockoff[MAX_SCAN_BLOCKS];
__device__ __align__(16) int2 g_edge[MAXT];   // {src, __float_as_int(edge weight)}
__device__ __align__(16) __half g_hf[(size_t)MAXN * FDIM];  // dinv-scaled gemm out (fp16)
__device__ __align__(16) float  g_h2[(size_t)MAXN * FDIM];  // spmm1 out (fp32)

// ------------------- dtype sniff helper (int64 vs int32 edge_index) -------------------
__device__ __forceinline__ int sniff_is64(const void* ei_raw, int N) {
    const long long* p64 = (const long long*)ei_raw;
    int ok = 1;
#pragma unroll
    for (int i = 0; i < 4; i++) {
        long long v = p64[i];
        if (v < 0 || v >= (long long)N) ok = 0;
    }
    return ok;
}

__device__ __forceinline__ float unpack_dinv(unsigned long long pk) {
    return rsqrtf((float)(pk & MASK52) * (1.0f / FIX_SCALE));
}

// ------------------- init: self loop -> count=1, deg=1.0 -------------------
__global__ void k_init(int N) {
    int i = blockIdx.x * blockDim.x + threadIdx.x;
    if (i < N) {
        g_dc[i] = (1ULL << 52) | (unsigned long long)(1u << 20);
        g_cursor[i] = 0;
    }
}

// ------------------- degree+count in ONE packed 64-bit atomic per edge ----------
__global__ void k_degcount(const void* __restrict__ ei_raw,
                           const float* __restrict__ ew, int E, int N) {
    __shared__ int is64;
    if (threadIdx.x == 0) is64 = sniff_is64(ei_raw, N);
    __syncthreads();
    int e = blockIdx.x * blockDim.x + threadIdx.x;
    if (e >= E) return;
    int c;
    if (is64) c = (int)((const long long*)ei_raw)[(size_t)E + e];
    else      c = ((const int*)ei_raw)[(size_t)E + e];
    unsigned long long pk =
        (1ULL << 52) | (unsigned long long)__float2uint_rn(ew[e] * FIX_SCALE);
    atomicAdd(&g_dc[c], pk);
}

// ------------------- scan pass 1: per-block exclusive scan of counts -------------------
__global__ void k_scan1(int N) {
    __shared__ int sm[256];
    int t = threadIdx.x;               // 256 threads, 4 elems each -> 1024 per block
    int base = blockIdx.x * SCAN_CHUNK + t * 4;
    int c0 = (base + 0 < N) ? (int)(g_dc[base + 0] >> 52) : 0;
    int c1 = (base + 1 < N) ? (int)(g_dc[base + 1] >> 52) : 0;
    int c2 = (base + 2 < N) ? (int)(g_dc[base + 2] >> 52) : 0;
    int c3 = (base + 3 < N) ? (int)(g_dc[base + 3] >> 52) : 0;
    int tsum = c0 + c1 + c2 + c3;
    sm[t] = tsum;
    __syncthreads();
    for (int off = 1; off < 256; off <<= 1) {
        int v = (t >= off) ? sm[t - off] : 0;
        __syncthreads();
        sm[t] += v;
        __syncthreads();
    }
    int pre = sm[t] - tsum;
    if (base + 0 < N) g_rowptr[base + 0] = pre;
    if (base + 1 < N) g_rowptr[base + 1] = pre + c0;
    if (base + 2 < N) g_rowptr[base + 2] = pre + c0 + c1;
    if (base + 3 < N) g_rowptr[base + 3] = pre + c0 + c1 + c2;
    if (t == 255) g_partial[blockIdx.x] = sm[255];
}

// ------------------- scan pass 2: scan block partials (single block) -------------------
__global__ void k_scan2(int nb, int N, int total) {
    __shared__ int sm[MAX_SCAN_BLOCKS];
    int t = threadIdx.x;               // blockDim = MAX_SCAN_BLOCKS
    int v = (t < nb) ? g_partial[t] : 0;
    sm[t] = v;
    __syncthreads();
    for (int off = 1; off < MAX_SCAN_BLOCKS; off <<= 1) {
        int u = (t >= off) ? sm[t - off] : 0;
        __syncthreads();
        sm[t] += u;
        __syncthreads();
    }
    if (t < nb) g_blockoff[t] = sm[t] - v;
    if (t == 0) g_rowptr[N] = total;
}

// ------------------- scan pass 3: add block offsets -------------------
__global__ void k_scan3(int N) {
    int i = blockIdx.x * blockDim.x + threadIdx.x;
    if (i < N) g_rowptr[i] += g_blockoff[i >> 10];
}

// ------------------- scatter into CSR: {src, raw weight} (NO dinv gathers) ----------
__global__ void k_scatter(const void* __restrict__ ei_raw,
                          const float* __restrict__ ew, int E, int N) {
    __shared__ int is64;
    if (threadIdx.x == 0) is64 = sniff_is64(ei_raw, N);
    __syncthreads();
    int idx = blockIdx.x * blockDim.x + threadIdx.x;
    int total = E + N;
    if (idx >= total) return;
    int r, c;
    float w;
    if (idx < E) {
        if (is64) {
            const long long* p64 = (const long long*)ei_raw;
            r = (int)p64[idx];
            c = (int)p64[(size_t)E + idx];
        } else {
            const int* p32 = (const int*)ei_raw;
            r = p32[idx];
            c = p32[(size_t)E + idx];
        }
        w = ew[idx];
    } else {
        r = c = idx - E;
        w = 1.0f;
    }
    int pos = g_rowptr[c] + atomicAdd(&g_cursor[c], 1);
    g_edge[pos] = make_int2(r, __float_as_int(w));
}

// ------------------- TF32 helpers -------------------
// RNA-round fp32 bits to tf32: +half-ulp of the 13 dropped bits. (Truncation
// would give a systematic -2^-10 bias that accumulates over K=128 -> ~1e-3.)
__device__ __forceinline__ uint32_t rna_tf32(float x) {
    return __float_as_uint(x) + 0x1000u;
}

__device__ __forceinline__ void mma_tf32(float& c0, float& c1, float& c2, float& c3,
                                         uint32_t a0, uint32_t a1, uint32_t a2, uint32_t a3,
                                         uint32_t b0, uint32_t b1) {
    asm volatile(
        "mma.sync.aligned.m16n8k8.row.col.f32.tf32.tf32.f32 "
        "{%0,%1,%2,%3}, {%4,%5,%6,%7}, {%8,%9}, {%0,%1,%2,%3};"
        : "+f"(c0), "+f"(c1), "+f"(c2), "+f"(c3)
        : "r"(a0), "r"(a1), "r"(a2), "r"(a3), "r"(b0), "r"(b1));
}

__device__ __forceinline__ void cp_async16(void* smem_dst, const void* gsrc, int bytes) {
    uint32_t d = (uint32_t)__cvta_generic_to_shared(smem_dst);
    asm volatile("cp.async.cg.shared.global [%0], [%1], 16, %2;"
                 :: "r"(d), "l"(gsrc), "r"(bytes));
}

// ------------------- TF32 tensor GEMM: g_hf[M,128] = dinv ⊙ (A[M,128] @ W[128,128]) --
// 64x128 block tile, 8 warps in 2x4; warp tile 32x32. 3-stage cp.async pipeline,
// k-chunks of 16, ONE __syncthreads per chunk. Epilogue folds dinv[row] into fp16 out.
#define AS 20    // A tile row stride (16 k + 4 pad)
#define WS 136   // W tile row stride
__global__ void __launch_bounds__(256) k_gemm(const float* __restrict__ Aopt,
                                              const float* __restrict__ W, int M) {
    const float* A = Aopt ? Aopt : g_h2;
    __half* C = g_hf;
    __shared__ float xs[3][64 * AS];    // 3*64*20*4  = 15360 B
    __shared__ float ws[3][16 * WS];    // 3*16*136*4 = 26112 B

    int tid = threadIdx.x;
    int wid = tid >> 5;
    int lane = tid & 31;
    int grp = lane >> 2;               // 0..7
    int sub = lane & 3;                // 0..3
    int m0 = blockIdx.x * 64;
    int wr = (wid >> 2) * 32;          // warp row base (0,32)
    int wc = (wid & 3) * 32;           // warp col base (0,32,64,96)

    float c[2][4][4];
#pragma unroll
    for (int f = 0; f < 2; f++)
#pragma unroll
        for (int nt = 0; nt < 4; nt++)
#pragma unroll
            for (int j = 0; j < 4; j++) c[f][nt][j] = 0.0f;

    auto loadA = [&](int k0, int buf) {
        int r = tid >> 2;
        int q = tid & 3;
        int bytes = (m0 + r < M) ? 16 : 0;
        cp_async16(&xs[buf][r * AS + q * 4],
                   A + (size_t)(m0 + r) * 128 + k0 + q * 4, bytes);
    };
    auto loadW = [&](int k0, int buf) {
#pragma unroll
        for (int i = 0; i < 2; i++) {
            int idx = tid + i * 256;
            int r = idx >> 5;
            int q = idx & 31;
            cp_async16(&ws[buf][r * WS + q * 4],
                       W + (size_t)(k0 + r) * 128 + q * 4, 16);
        }
    };

    loadA(0, 0);  loadW(0, 0);  asm volatile("cp.async.commit_group;");
    loadA(16, 1); loadW(16, 1); asm volatile("cp.async.commit_group;");

#pragma unroll
    for (int ch = 0; ch < 8; ch++) {
        int buf = ch % 3;
        if (ch < 7) asm volatile("cp.async.wait_group 1;");
        else        asm volatile("cp.async.wait_group 0;");
        __syncthreads();
        if (ch + 2 < 8) {
            int nb = (ch + 2) % 3;
            loadA((ch + 2) * 16, nb);
            loadW((ch + 2) * 16, nb);
            asm volatile("cp.async.commit_group;");
        }

#pragma unroll
        for (int kk = 0; kk < 2; kk++) {
            int kb = kk * 8;
            uint32_t a[2][4];
#pragma unroll
            for (int f = 0; f < 2; f++) {
                int rb = wr + f * 16;
                a[f][0] = rna_tf32(xs[buf][(rb + grp) * AS + kb + sub]);
                a[f][1] = rna_tf32(xs[buf][(rb + grp + 8) * AS + kb + sub]);
                a[f][2] = rna_tf32(xs[buf][(rb + grp) * AS + kb + sub + 4]);
                a[f][3] = rna_tf32(xs[buf][(rb + grp + 8) * AS + kb + sub + 4]);
            }
#pragma unroll
            for (int nt = 0; nt < 4; nt++) {
                uint32_t b0 = rna_tf32(ws[buf][(kb + sub) * WS + wc + nt * 8 + grp]);
                uint32_t b1 = rna_tf32(ws[buf][(kb + sub + 4) * WS + wc + nt * 8 + grp]);
                mma_tf32(c[0][nt][0], c[0][nt][1], c[0][nt][2], c[0][nt][3],
                         a[0][0], a[0][1], a[0][2], a[0][3], b0, b1);
                mma_tf32(c[1][nt][0], c[1][nt][1], c[1][nt][2], c[1][nt][3],
                         a[1][0], a[1][1], a[1][2], a[1][3], b0, b1);
            }
        }
    }

    // epilogue: scale row by dinv[row], emit fp16
#pragma unroll
    for (int f = 0; f < 2; f++) {
        int r0 = m0 + wr + f * 16 + grp;
        int r1 = r0 + 8;
        float d0 = (r0 < M) ? unpack_dinv(g_dc[r0]) : 0.0f;
        float d1 = (r1 < M) ? unpack_dinv(g_dc[r1]) : 0.0f;
#pragma unroll
        for (int nt = 0; nt < 4; nt++) {
            int cb = wc + nt * 8 + 2 * sub;
            if (r0 < M)
                *(half2*)(C + (size_t)r0 * 128 + cb) =
                    __floats2half2_rn(d0 * c[f][nt][0], d0 * c[f][nt][1]);
            if (r1 < M)
                *(half2*)(C + (size_t)r1 * 128 + cb) =
                    __floats2half2_rn(d1 * c[f][nt][2], d1 * c[f][nt][3]);
        }
    }
}

// ------------------- SpMM: out[c,:] = dinv[c] * sum w*g_hf[src,:] + bias (+relu) ----
__global__ void __launch_bounds__(256) k_spmm(const float* __restrict__ bias,
                                              float* outOpt, int N, int doRelu) {
    const uint2* h = (const uint2*)g_hf;
    float* out = outOpt ? outOpt : g_h2;
    int warp = (blockIdx.x * blockDim.x + threadIdx.x) >> 5;
    int lane = threadIdx.x & 31;
    if (warp >= N) return;
    int beg = g_rowptr[warp];
    int end = g_rowptr[warp + 1];

    float4 acc = make_float4(0.f, 0.f, 0.f, 0.f);
    int e = beg;

#define GATHER_FMA(P, V)                                            \
    do {                                                            \
        float2 f0 = __half22float2(*(const half2*)&(P).x);          \
        float2 f1 = __half22float2(*(const half2*)&(P).y);          \
        acc.x += (V) * f0.x; acc.y += (V) * f0.y;                   \
        acc.z += (V) * f1.x; acc.w += (V) * f1.y;                   \
    } while (0)

    if ((e & 1) && e < end) {
        int2 p = g_edge[e];
        uint2 hv = h[(size_t)p.x * 32 + lane];
        GATHER_FMA(hv, __int_as_float(p.y));
        e++;
    }

    for (; e + 8 <= end; e += 8) {
        int4 q0 = *(const int4*)&g_edge[e + 0];
        int4 q1 = *(const int4*)&g_edge[e + 2];
        int4 q2 = *(const int4*)&g_edge[e + 4];
        int4 q3 = *(const int4*)&g_edge[e + 6];
        uint2 h0 = h[(size_t)q0.x * 32 + lane];
        uint2 h1 = h[(size_t)q0.z * 32 + lane];
        uint2 h2 = h[(size_t)q1.x * 32 + lane];
        uint2 h3 = h[(size_t)q1.z * 32 + lane];
        uint2 h4 = h[(size_t)q2.x * 32 + lane];
        uint2 h5 = h[(size_t)q2.z * 32 + lane];
        uint2 h6 = h[(size_t)q3.x * 32 + lane];
        uint2 h7 = h[(size_t)q3.z * 32 + lane];
        GATHER_FMA(h0, __int_as_float(q0.y));
        GATHER_FMA(h1, __int_as_float(q0.w));
        GATHER_FMA(h2, __int_as_float(q1.y));
        GATHER_FMA(h3, __int_as_float(q1.w));
        GATHER_FMA(h4, __int_as_float(q2.y));
        GATHER_FMA(h5, __int_as_float(q2.w));
        GATHER_FMA(h6, __int_as_float(q3.y));
        GATHER_FMA(h7, __int_as_float(q3.w));
    }

    for (; e + 2 <= end; e += 2) {
        int4 q0 = *(const int4*)&g_edge[e];
        uint2 h0 = h[(size_t)q0.x * 32 + lane];
        uint2 h1 = h[(size_t)q0.z * 32 + lane];
        GATHER_FMA(h0, __int_as_float(q0.y));
        GATHER_FMA(h1, __int_as_float(q0.w));
    }
    if (e < end) {
        int2 p = g_edge[e];
        uint2 hv = h[(size_t)p.x * 32 + lane];
        GATHER_FMA(hv, __int_as_float(p.y));
    }
#undef GATHER_FMA

    float dinv_c = unpack_dinv(g_dc[warp]);
    float4 b = ((const float4*)bias)[lane];
    float4 r;
    r.x = dinv_c * acc.x + b.x;
    r.y = dinv_c * acc.y + b.y;
    r.z = dinv_c * acc.z + b.z;
    r.w = dinv_c * acc.w + b.w;
    if (doRelu) {
        r.x = fmaxf(r.x, 0.f);
        r.y = fmaxf(r.y, 0.f);
        r.z = fmaxf(r.z, 0.f);
        r.w = fmaxf(r.w, 0.f);
    }
    *(float4*)(out + (size_t)warp * 128 + lane * 4) = r;
}

// ------------------- launch -------------------
// Launch #4 = gemm1 (needs g_dc from degcount; ready).
extern "C" void kernel_launch(void* const* d_in, const int* in_sizes, int n_in,
                              void* d_out, int out_size) {
    const float* x  = (const float*)d_in[0];
    const void*  ei = (const void*)d_in[1];
    const float* ew = (const float*)d_in[2];
    const float* W1 = (const float*)d_in[3];
    const float* b1 = (const float*)d_in[4];
    const float* W2 = (const float*)d_in[5];
    const float* b2 = (const float*)d_in[6];
    float* out = (float*)d_out;

    const int E = in_sizes[2];          // 3200000
    const int N = in_sizes[0] / FDIM;   // 100000
    const int T = E + N;

    int gemmGrid = (N + 63) / 64;
    int spmmGrid = (N * 32 + 255) / 256;
    int nb = (N + SCAN_CHUNK - 1) / SCAN_CHUNK;

    k_init<<<(N + 255) / 256, 256>>>(N);                    // #1
    k_degcount<<<(E + 255) / 256, 256>>>(ei, ew, E, N);     // #2
    k_scan1<<<nb, 256>>>(N);                                // #3
    k_gemm<<<gemmGrid, 256>>>(x, W1, N);                    // #4  <- ncu capture
    k_scan2<<<1, MAX_SCAN_BLOCKS>>>(nb, N, T);              // #5
    k_scan3<<<(N + 255) / 256, 256>>>(N);                   // #6
    k_scatter<<<(T + 255) / 256, 256>>>(ei, ew, E, N);      // #7

    k_spmm<<<spmmGrid, 256>>>(b1, nullptr, N, 1);           // #8  g_hf -> g_h2
    k_gemm<<<gemmGrid, 256>>>(nullptr, W2, N);              // #9  g_h2 -> g_hf
    k_spmm<<<spmmGrid, 256>>>(b2, out, N, 0);               // #10 g_hf -> out
}

// round 14
// speedup vs baseline: 239.5901x; 1.0244x over previous
#include <cuda_runtime.h>
#include <cuda_fp16.h>
#include <stdint.h>

#define MAXN 100000
#define MAXE 3200000
#define MAXT (MAXE + MAXN)
#define FDIM 128
#define SCAN_CHUNK 1024
#define MAX_SCAN_BLOCKS 128  // ceil(100000/1024)=98
#define FIX_SCALE 1048576.0f          // 2^20 fixed-point for weighted degree
#define MASK52 ((1ULL << 52) - 1)

// ------------------- device scratch -------------------
// NOTE: these symbols must ONLY be referenced from device code. Passing them
// as kernel args from host yields the host shadow symbol, which GB300's ATS
// serves from Grace DRAM at ~200 GB/s (the R2-R5 17.9ms bug).
__device__ unsigned long long g_dc[MAXN];     // [count:52..63][deg*2^20:0..51]
__device__ int   g_rowptr[MAXN + 1];
__device__ int   g_cursor[MAXN];
__device__ int   g_partial[MAX_SCAN_BLOCKS];
__device__ int   g_blockoff[MAX_SCAN_BLOCKS];
__device__ __align__(16) int2 g_edge[MAXT];   // {src, __float_as_int(edge weight)}
__device__ __align__(16) __half g_hf[(size_t)MAXN * FDIM];  // dinv-scaled gemm out (fp16)
__device__ __align__(16) float  g_h2[(size_t)MAXN * FDIM];  // spmm1 out (fp32)

// ------------------- dtype sniff helper (int64 vs int32 edge_index) -------------------
__device__ __forceinline__ int sniff_is64(const void* ei_raw, int N) {
    const long long* p64 = (const long long*)ei_raw;
    int ok = 1;
#pragma unroll
    for (int i = 0; i < 4; i++) {
        long long v = p64[i];
        if (v < 0 || v >= (long long)N) ok = 0;
    }
    return ok;
}

__device__ __forceinline__ float unpack_dinv(unsigned long long pk) {
    return rsqrtf((float)(pk & MASK52) * (1.0f / FIX_SCALE));
}

// ------------------- init: self loop -> count=1, deg=1.0 -------------------
__global__ void k_init(int N) {
    int i = blockIdx.x * blockDim.x + threadIdx.x;
    if (i < N) {
        g_dc[i] = (1ULL << 52) | (unsigned long long)(1u << 20);
        g_cursor[i] = 0;
    }
}

// ------------------- degree+count: ONE packed 64-bit atomic; 2 edges/thread ---------
__global__ void k_degcount(const void* __restrict__ ei_raw,
                           const float* __restrict__ ew, int E, int N) {
    __shared__ int is64;
    if (threadIdx.x == 0) is64 = sniff_is64(ei_raw, N);
    __syncthreads();
    int t = blockIdx.x * blockDim.x + threadIdx.x;
    int e = t * 2;
    if (e >= E) return;
    int c0, c1 = -1;
    if (is64) {
        const long long* p64 = (const long long*)ei_raw;
        c0 = (int)p64[(size_t)E + e];
        if (e + 1 < E) c1 = (int)p64[(size_t)E + e + 1];
    } else {
        const int* p32 = (const int*)ei_raw;
        int2 cc = *(const int2*)(p32 + (size_t)E + e);   // E even -> aligned
        c0 = cc.x;
        if (e + 1 < E) c1 = cc.y;
    }
    float2 wv = *(const float2*)(ew + e);
    unsigned long long pk0 =
        (1ULL << 52) | (unsigned long long)__float2uint_rn(wv.x * FIX_SCALE);
    atomicAdd(&g_dc[c0], pk0);
    if (c1 >= 0) {
        unsigned long long pk1 =
            (1ULL << 52) | (unsigned long long)__float2uint_rn(wv.y * FIX_SCALE);
        atomicAdd(&g_dc[c1], pk1);
    }
}

// ------------------- scan pass 1: per-block exclusive scan of counts -------------------
__global__ void k_scan1(int N) {
    __shared__ int sm[256];
    int t = threadIdx.x;               // 256 threads, 4 elems each -> 1024 per block
    int base = blockIdx.x * SCAN_CHUNK + t * 4;
    int c0 = (base + 0 < N) ? (int)(g_dc[base + 0] >> 52) : 0;
    int c1 = (base + 1 < N) ? (int)(g_dc[base + 1] >> 52) : 0;
    int c2 = (base + 2 < N) ? (int)(g_dc[base + 2] >> 52) : 0;
    int c3 = (base + 3 < N) ? (int)(g_dc[base + 3] >> 52) : 0;
    int tsum = c0 + c1 + c2 + c3;
    sm[t] = tsum;
    __syncthreads();
    for (int off = 1; off < 256; off <<= 1) {
        int v = (t >= off) ? sm[t - off] : 0;
        __syncthreads();
        sm[t] += v;
        __syncthreads();
    }
    int pre = sm[t] - tsum;
    if (base + 0 < N) g_rowptr[base + 0] = pre;
    if (base + 1 < N) g_rowptr[base + 1] = pre + c0;
    if (base + 2 < N) g_rowptr[base + 2] = pre + c0 + c1;
    if (base + 3 < N) g_rowptr[base + 3] = pre + c0 + c1 + c2;
    if (t == 255) g_partial[blockIdx.x] = sm[255];
}

// ------------------- scan pass 2: scan block partials (single block) -------------------
__global__ void k_scan2(int nb, int N, int total) {
    __shared__ int sm[MAX_SCAN_BLOCKS];
    int t = threadIdx.x;               // blockDim = MAX_SCAN_BLOCKS
    int v = (t < nb) ? g_partial[t] : 0;
    sm[t] = v;
    __syncthreads();
    for (int off = 1; off < MAX_SCAN_BLOCKS; off <<= 1) {
        int u = (t >= off) ? sm[t - off] : 0;
        __syncthreads();
        sm[t] += u;
        __syncthreads();
    }
    if (t < nb) g_blockoff[t] = sm[t] - v;
    if (t == 0) g_rowptr[N] = total;
}

// ------------------- scan pass 3: add block offsets -------------------
__global__ void k_scan3(int N) {
    int i = blockIdx.x * blockDim.x + threadIdx.x;
    if (i < N) g_rowptr[i] += g_blockoff[i >> 10];
}

// ------------------- scatter into CSR: {src, raw weight}; 2 edges/thread ------------
__global__ void k_scatter(const void* __restrict__ ei_raw,
                          const float* __restrict__ ew, int E, int N) {
    __shared__ int is64;
    if (threadIdx.x == 0) is64 = sniff_is64(ei_raw, N);
    __syncthreads();
    int t = blockIdx.x * blockDim.x + threadIdx.x;
    int Eh = (E + 1) >> 1;                       // threads covering edge pairs
    if (t < Eh) {
        int e = t * 2;
        int r0, c0, r1 = -1, c1 = -1;
        if (is64) {
            const long long* p64 = (const long long*)ei_raw;
            r0 = (int)p64[e];
            c0 = (int)p64[(size_t)E + e];
            if (e + 1 < E) {
                r1 = (int)p64[e + 1];
                c1 = (int)p64[(size_t)E + e + 1];
            }
        } else {
            const int* p32 = (const int*)ei_raw;
            int2 rr = *(const int2*)(p32 + e);
            int2 cc = *(const int2*)(p32 + (size_t)E + e);
            r0 = rr.x; c0 = cc.x;
            if (e + 1 < E) { r1 = rr.y; c1 = cc.y; }
        }
        float2 wv = *(const float2*)(ew + e);
        int pos0 = g_rowptr[c0] + atomicAdd(&g_cursor[c0], 1);
        g_edge[pos0] = make_int2(r0, __float_as_int(wv.x));
        if (r1 >= 0) {
            int pos1 = g_rowptr[c1] + atomicAdd(&g_cursor[c1], 1);
            g_edge[pos1] = make_int2(r1, __float_as_int(wv.y));
        }
    } else {
        int i = t - Eh;                          // self loops
        if (i < N) {
            int pos = g_rowptr[i] + atomicAdd(&g_cursor[i], 1);
            g_edge[pos] = make_int2(i, __float_as_int(1.0f));
        }
    }
}

// ------------------- TF32 helpers -------------------
// RNA-round fp32 bits to tf32: +half-ulp of the 13 dropped bits. (Truncation
// would give a systematic -2^-10 bias that accumulates over K=128 -> ~1e-3.)
__device__ __forceinline__ uint32_t rna_tf32(float x) {
    return __float_as_uint(x) + 0x1000u;
}

__device__ __forceinline__ void mma_tf32(float& c0, float& c1, float& c2, float& c3,
                                         uint32_t a0, uint32_t a1, uint32_t a2, uint32_t a3,
                                         uint32_t b0, uint32_t b1) {
    asm volatile(
        "mma.sync.aligned.m16n8k8.row.col.f32.tf32.tf32.f32 "
        "{%0,%1,%2,%3}, {%4,%5,%6,%7}, {%8,%9}, {%0,%1,%2,%3};"
        : "+f"(c0), "+f"(c1), "+f"(c2), "+f"(c3)
        : "r"(a0), "r"(a1), "r"(a2), "r"(a3), "r"(b0), "r"(b1));
}

__device__ __forceinline__ void cp_async16(void* smem_dst, const void* gsrc, int bytes) {
    uint32_t d = (uint32_t)__cvta_generic_to_shared(smem_dst);
    asm volatile("cp.async.cg.shared.global [%0], [%1], 16, %2;"
                 :: "r"(d), "l"(gsrc), "r"(bytes));
}

// ------------------- TF32 tensor GEMM: g_hf[M,128] = dinv ⊙ (A[M,128] @ W[128,128]) --
// 64x128 block tile, 8 warps in 2x4; warp tile 32x32. 3-stage cp.async pipeline,
// k-chunks of 16, ONE __syncthreads per chunk. Epilogue folds dinv[row] into fp16 out.
#define AS 20    // A tile row stride (16 k + 4 pad)
#define WS 136   // W tile row stride
__global__ void __launch_bounds__(256) k_gemm(const float* __restrict__ Aopt,
                                              const float* __restrict__ W, int M) {
    const float* A = Aopt ? Aopt : g_h2;
    __half* C = g_hf;
    __shared__ float xs[3][64 * AS];    // 3*64*20*4  = 15360 B
    __shared__ float ws[3][16 * WS];    // 3*16*136*4 = 26112 B

    int tid = threadIdx.x;
    int wid = tid >> 5;
    int lane = tid & 31;
    int grp = lane >> 2;               // 0..7
    int sub = lane & 3;                // 0..3
    int m0 = blockIdx.x * 64;
    int wr = (wid >> 2) * 32;          // warp row base (0,32)
    int wc = (wid & 3) * 32;           // warp col base (0,32,64,96)

    float c[2][4][4];
#pragma unroll
    for (int f = 0; f < 2; f++)
#pragma unroll
        for (int nt = 0; nt < 4; nt++)
#pragma unroll
            for (int j = 0; j < 4; j++) c[f][nt][j] = 0.0f;

    auto loadA = [&](int k0, int buf) {
        int r = tid >> 2;
        int q = tid & 3;
        int bytes = (m0 + r < M) ? 16 : 0;
        cp_async16(&xs[buf][r * AS + q * 4],
                   A + (size_t)(m0 + r) * 128 + k0 + q * 4, bytes);
    };
    auto loadW = [&](int k0, int buf) {
#pragma unroll
        for (int i = 0; i < 2; i++) {
            int idx = tid + i * 256;
            int r = idx >> 5;
            int q = idx & 31;
            cp_async16(&ws[buf][r * WS + q * 4],
                       W + (size_t)(k0 + r) * 128 + q * 4, 16);
        }
    };

    loadA(0, 0);  loadW(0, 0);  asm volatile("cp.async.commit_group;");
    loadA(16, 1); loadW(16, 1); asm volatile("cp.async.commit_group;");

#pragma unroll
    for (int ch = 0; ch < 8; ch++) {
        int buf = ch % 3;
        if (ch < 7) asm volatile("cp.async.wait_group 1;");
        else        asm volatile("cp.async.wait_group 0;");
        __syncthreads();
        if (ch + 2 < 8) {
            int nb = (ch + 2) % 3;
            loadA((ch + 2) * 16, nb);
            loadW((ch + 2) * 16, nb);
            asm volatile("cp.async.commit_group;");
        }

#pragma unroll
        for (int kk = 0; kk < 2; kk++) {
            int kb = kk * 8;
            uint32_t a[2][4];
#pragma unroll
            for (int f = 0; f < 2; f++) {
                int rb = wr + f * 16;
                a[f][0] = rna_tf32(xs[buf][(rb + grp) * AS + kb + sub]);
                a[f][1] = rna_tf32(xs[buf][(rb + grp + 8) * AS + kb + sub]);
                a[f][2] = rna_tf32(xs[buf][(rb + grp) * AS + kb + sub + 4]);
                a[f][3] = rna_tf32(xs[buf][(rb + grp + 8) * AS + kb + sub + 4]);
            }
#pragma unroll
            for (int nt = 0; nt < 4; nt++) {
                uint32_t b0 = rna_tf32(ws[buf][(kb + sub) * WS + wc + nt * 8 + grp]);
                uint32_t b1 = rna_tf32(ws[buf][(kb + sub + 4) * WS + wc + nt * 8 + grp]);
                mma_tf32(c[0][nt][0], c[0][nt][1], c[0][nt][2], c[0][nt][3],
                         a[0][0], a[0][1], a[0][2], a[0][3], b0, b1);
                mma_tf32(c[1][nt][0], c[1][nt][1], c[1][nt][2], c[1][nt][3],
                         a[1][0], a[1][1], a[1][2], a[1][3], b0, b1);
            }
        }
    }

    // epilogue: scale row by dinv[row], emit fp16
#pragma unroll
    for (int f = 0; f < 2; f++) {
        int r0 = m0 + wr + f * 16 + grp;
        int r1 = r0 + 8;
        float d0 = (r0 < M) ? unpack_dinv(g_dc[r0]) : 0.0f;
        float d1 = (r1 < M) ? unpack_dinv(g_dc[r1]) : 0.0f;
#pragma unroll
        for (int nt = 0; nt < 4; nt++) {
            int cb = wc + nt * 8 + 2 * sub;
            if (r0 < M)
                *(half2*)(C + (size_t)r0 * 128 + cb) =
                    __floats2half2_rn(d0 * c[f][nt][0], d0 * c[f][nt][1]);
            if (r1 < M)
                *(half2*)(C + (size_t)r1 * 128 + cb) =
                    __floats2half2_rn(d1 * c[f][nt][2], d1 * c[f][nt][3]);
        }
    }
}

// ------------------- SpMM: out[c,:] = dinv[c] * sum w*g_hf[src,:] + bias (+relu) ----
__global__ void __launch_bounds__(256) k_spmm(const float* __restrict__ bias,
                                              float* outOpt, int N, int doRelu) {
    const uint2* h = (const uint2*)g_hf;
    float* out = outOpt ? outOpt : g_h2;
    int warp = (blockIdx.x * blockDim.x + threadIdx.x) >> 5;
    int lane = threadIdx.x & 31;
    if (warp >= N) return;
    int beg = g_rowptr[warp];
    int end = g_rowptr[warp + 1];

    float4 acc = make_float4(0.f, 0.f, 0.f, 0.f);
    int e = beg;

#define GATHER_FMA(P, V)                                            \
    do {                                                            \
        float2 f0 = __half22float2(*(const half2*)&(P).x);          \
        float2 f1 = __half22float2(*(const half2*)&(P).y);          \
        acc.x += (V) * f0.x; acc.y += (V) * f0.y;                   \
        acc.z += (V) * f1.x; acc.w += (V) * f1.y;                   \
    } while (0)

    if ((e & 1) && e < end) {
        int2 p = g_edge[e];
        uint2 hv = h[(size_t)p.x * 32 + lane];
        GATHER_FMA(hv, __int_as_float(p.y));
        e++;
    }

    for (; e + 8 <= end; e += 8) {
        int4 q0 = *(const int4*)&g_edge[e + 0];
        int4 q1 = *(const int4*)&g_edge[e + 2];
        int4 q2 = *(const int4*)&g_edge[e + 4];
        int4 q3 = *(const int4*)&g_edge[e + 6];
        uint2 h0 = h[(size_t)q0.x * 32 + lane];
        uint2 h1 = h[(size_t)q0.z * 32 + lane];
        uint2 h2 = h[(size_t)q1.x * 32 + lane];
        uint2 h3 = h[(size_t)q1.z * 32 + lane];
        uint2 h4 = h[(size_t)q2.x * 32 + lane];
        uint2 h5 = h[(size_t)q2.z * 32 + lane];
        uint2 h6 = h[(size_t)q3.x * 32 + lane];
        uint2 h7 = h[(size_t)q3.z * 32 + lane];
        GATHER_FMA(h0, __int_as_float(q0.y));
        GATHER_FMA(h1, __int_as_float(q0.w));
        GATHER_FMA(h2, __int_as_float(q1.y));
        GATHER_FMA(h3, __int_as_float(q1.w));
        GATHER_FMA(h4, __int_as_float(q2.y));
        GATHER_FMA(h5, __int_as_float(q2.w));
        GATHER_FMA(h6, __int_as_float(q3.y));
        GATHER_FMA(h7, __int_as_float(q3.w));
    }

    for (; e + 2 <= end; e += 2) {
        int4 q0 = *(const int4*)&g_edge[e];
        uint2 h0 = h[(size_t)q0.x * 32 + lane];
        uint2 h1 = h[(size_t)q0.z * 32 + lane];
        GATHER_FMA(h0, __int_as_float(q0.y));
        GATHER_FMA(h1, __int_as_float(q0.w));
    }
    if (e < end) {
        int2 p = g_edge[e];
        uint2 hv = h[(size_t)p.x * 32 + lane];
        GATHER_FMA(hv, __int_as_float(p.y));
    }
#undef GATHER_FMA

    float dinv_c = unpack_dinv(g_dc[warp]);
    float4 b = ((const float4*)bias)[lane];
    float4 r;
    r.x = dinv_c * acc.x + b.x;
    r.y = dinv_c * acc.y + b.y;
    r.z = dinv_c * acc.z + b.z;
    r.w = dinv_c * acc.w + b.w;
    if (doRelu) {
        r.x = fmaxf(r.x, 0.f);
        r.y = fmaxf(r.y, 0.f);
        r.z = fmaxf(r.z, 0.f);
        r.w = fmaxf(r.w, 0.f);
    }
    *(float4*)(out + (size_t)warp * 128 + lane * 4) = r;
}

// ------------------- launch -------------------
// Fork-join DAG (captured as a multi-branch graph):
//   main: init -> degcount -> [fork] scan1 -> scan2 -> scan3 -> scatter -> [join] spmm1 -> gemm2 -> spmm2
//   side:                       gemm1 (needs only g_dc)
extern "C" void kernel_launch(void* const* d_in, const int* in_sizes, int n_in,
                              void* d_out, int out_size) {
    const float* x  = (const float*)d_in[0];
    const void*  ei = (const void*)d_in[1];
    const float* ew = (const float*)d_in[2];
    const float* W1 = (const float*)d_in[3];
    const float* b1 = (const float*)d_in[4];
    const float* W2 = (const float*)d_in[5];
    const float* b2 = (const float*)d_in[6];
    float* out = (float*)d_out;

    const int E = in_sizes[2];          // 3200000
    const int N = in_sizes[0] / FDIM;   // 100000
    const int T = E + N;

    // Created once on the first (uncaptured correctness) call; reused under capture.
    static cudaStream_t s1 = nullptr;
    static cudaEvent_t evFork = nullptr, evJoin = nullptr;
    if (s1 == nullptr) {
        cudaStreamCreateWithFlags(&s1, cudaStreamNonBlocking);
        cudaEventCreateWithFlags(&evFork, cudaEventDisableTiming);
        cudaEventCreateWithFlags(&evJoin, cudaEventDisableTiming);
    }

    int gemmGrid = (N + 63) / 64;
    int spmmGrid = (N * 32 + 255) / 256;
    int nb = (N + SCAN_CHUNK - 1) / SCAN_CHUNK;
    int dcGrid = ((E + 1) / 2 + 255) / 256;
    int scGrid = (((E + 1) / 2 + N) + 255) / 256;

    k_init<<<(N + 255) / 256, 256>>>(N);
    k_degcount<<<dcGrid, 256>>>(ei, ew, E, N);

    // fork: gemm1 only needs g_dc (degcount) — overlap with CSR build
    cudaEventRecord(evFork, 0);
    cudaStreamWaitEvent(s1, evFork, 0);
    k_gemm<<<gemmGrid, 256, 0, s1>>>(x, W1, N);
    cudaEventRecord(evJoin, s1);

    k_scan1<<<nb, 256>>>(N);
    k_scan2<<<1, MAX_SCAN_BLOCKS>>>(nb, N, T);
    k_scan3<<<(N + 255) / 256, 256>>>(N);
    k_scatter<<<scGrid, 256>>>(ei, ew, E, N);

    // join: spmm1 needs both scatter (CSR) and gemm1 (g_hf)
    cudaStreamWaitEvent(0, evJoin, 0);
    k_spmm<<<spmmGrid, 256>>>(b1, nullptr, N, 1);   // g_hf -> g_h2
    k_gemm<<<gemmGrid, 256>>>(nullptr, W2, N);      // g_h2 -> g_hf
    k_spmm<<<spmmGrid, 256>>>(b2, out, N, 0);       // g_hf -> out
}